// round 14
// baseline (speedup 1.0000x reference)
#include <cuda_runtime.h>
#include <cstdint>
#include <cstddef>

#define HW   4096
#define Dh   128
#define Cc   256
#define NB   4
#define ST   136   // theta smem row stride (bf16 elems)
#define STB  72    // phi/g/X chunk smem row stride (bf16 elems)
#define BK   64    // key chunk per flash iteration
#define KSPLIT 4
#define NITER (HW/KSPLIT/BK)   // 16

// ======================= helpers =======================
__device__ __forceinline__ uint32_t smem_u32(const void* p) {
  uint32_t a;
  asm("{ .reg .u64 t; cvta.to.shared.u64 t, %1; cvt.u32.u64 %0, t; }" : "=r"(a) : "l"(p));
  return a;
}
__device__ __forceinline__ void ldm_x4(uint32_t a, uint32_t* r) {
  asm volatile("ldmatrix.sync.aligned.m8n8.x4.shared.b16 {%0,%1,%2,%3}, [%4];"
               : "=r"(r[0]), "=r"(r[1]), "=r"(r[2]), "=r"(r[3]) : "r"(a));
}
__device__ __forceinline__ void ldm_x4_t(uint32_t a, uint32_t* r) {
  asm volatile("ldmatrix.sync.aligned.m8n8.x4.trans.shared.b16 {%0,%1,%2,%3}, [%4];"
               : "=r"(r[0]), "=r"(r[1]), "=r"(r[2]), "=r"(r[3]) : "r"(a));
}
__device__ __forceinline__ void hmma(float* d, const uint32_t* a, const uint32_t* b) {
  asm volatile("mma.sync.aligned.m16n8k16.row.col.f32.bf16.bf16.f32 "
               "{%0,%1,%2,%3}, {%4,%5,%6,%7}, {%8,%9}, {%0,%1,%2,%3};"
               : "+f"(d[0]), "+f"(d[1]), "+f"(d[2]), "+f"(d[3])
               : "r"(a[0]), "r"(a[1]), "r"(a[2]), "r"(a[3]), "r"(b[0]), "r"(b[1]));
}
__device__ __forceinline__ void cpasync16(uint32_t dst, const void* src) {
  asm volatile("cp.async.cg.shared.global [%0], [%1], 16;" :: "r"(dst), "l"(src));
}
#define CP_COMMIT() asm volatile("cp.async.commit_group;" ::: "memory")
#define CP_WAIT0()  asm volatile("cp.async.wait_group 0;" ::: "memory")
#define CP_WAIT1()  asm volatile("cp.async.wait_group 1;" ::: "memory")

// bf16 RN-even bits (kept in HIGH half, low 16 zero) — pure int ops, no CVT
__device__ __forceinline__ uint32_t hbits(float x) {
  uint32_t u = __float_as_uint(x);
  return (u + 0x7FFFu + ((u >> 16) & 1u)) & 0xFFFF0000u;
}
// fast exp on FMA/ALU pipes (no MUFU)
__device__ __forceinline__ float fexp(float x) {
  float t = x * 1.4426950408889634f;
  float r = t + 12582912.0f;
  int   n = __float_as_int(r) - 0x4B400000;
  float f = t - (r - 12582912.0f);
  float p = 1.540353e-4f;
  p = fmaf(p, f, 1.3333558e-3f);
  p = fmaf(p, f, 9.6181291e-3f);
  p = fmaf(p, f, 5.5504109e-2f);
  p = fmaf(p, f, 2.4022651e-1f);
  p = fmaf(p, f, 6.9314718e-1f);
  p = fmaf(p, f, 1.0f);
  n = max(n, -126);
  return p * __int_as_float((n + 127) << 23);
}
// RN pack (x,y) -> bf16x2 hi + residual bf16x2 lo (cold paths)
__device__ __forceinline__ void packpair(float x, float y, uint32_t& h, uint32_t& l) {
  uint32_t hx = hbits(x), hy = hbits(y);
  h = __byte_perm(hx, hy, 0x7632);
  float lx = x - __uint_as_float(hx), ly = y - __uint_as_float(hy);
  l = __byte_perm(hbits(lx), hbits(ly), 0x7632);
}
// TRUNC pack (hot PV loop; valid when dropped lo*lo term has random sign)
__device__ __forceinline__ void packpair_t(float x, float y, uint32_t& h, uint32_t& l) {
  uint32_t ux = __float_as_uint(x), uy = __float_as_uint(y);
  h = __byte_perm(ux, uy, 0x7632);
  float lx = x - __uint_as_float(ux & 0xFFFF0000u);
  float ly = y - __uint_as_float(uy & 0xFFFF0000u);
  l = __byte_perm(__float_as_uint(lx), __float_as_uint(ly), 0x7632);
}
// split 8 floats -> bf16 hi/lo packed stores (RN)
__device__ __forceinline__ void split8_store(const float* v, unsigned short* hiP,
                                             unsigned short* loP) {
  uint32_t hw[4], lw[4];
  #pragma unroll
  for (int i = 0; i < 4; i++) {
    uint32_t h0 = hbits(v[2*i]), h1 = hbits(v[2*i+1]);
    hw[i] = __byte_perm(h0, h1, 0x7632);
    float l0 = v[2*i]   - __uint_as_float(h0);
    float l1 = v[2*i+1] - __uint_as_float(h1);
    lw[i] = __byte_perm(hbits(l0), hbits(l1), 0x7632);
  }
  *(uint4*)hiP = make_uint4(hw[0], hw[1], hw[2], hw[3]);
  *(uint4*)loP = make_uint4(lw[0], lw[1], lw[2], lw[3]);
}

// ---------------- scratch (device globals, no allocation) ----------------
#define XN ((size_t)NB*Cc*HW)   // 4194304 elems per source tensor
__device__ unsigned short d_x_hi[2*XN];              // split left/right [src][b][c][hw]
__device__ unsigned short d_x_lo[2*XN];
__device__ unsigned short d_w_hi[3*128*256];         // split weights [proj][d][c]
__device__ unsigned short d_w_lo[3*128*256];
__device__ unsigned short d_th_hi[(size_t)8*Dh*HW];  // theta^T [sb][d][q]
__device__ unsigned short d_th_lo[(size_t)8*Dh*HW];
__device__ unsigned short d_ph_hi[(size_t)8*Dh*HW];  // phi^T   [sb][d][key]
__device__ unsigned short d_ph_lo[(size_t)8*Dh*HW];
__device__ unsigned short d_g_hi [(size_t)8*Dh*HW];  // g^T     [sb][d][k]
__device__ unsigned short d_g_lo [(size_t)8*Dh*HW];
__device__ unsigned short d_af_hi[(size_t)8*HW*Dh];  // after [sb][q][d] (split)
__device__ unsigned short d_af_lo[(size_t)8*HW*Dh];
__device__ float  d_op [(size_t)KSPLIT*8*HW*Dh];     // unnormalized O partials
__device__ float2 d_lcp[(size_t)KSPLIT*8*HW];        // (l, c) partials
__device__ float  d_y    [(size_t)8*Cc*HW];
__device__ float2 d_bn   [2*Cc];

// ======================= input conversion kernels =======================
__global__ __launch_bounds__(256) void convx_kernel(
    const float* __restrict__ left, const float* __restrict__ right)
{
  const float* src = blockIdx.y ? right : left;
  size_t off = ((size_t)blockIdx.x*256 + threadIdx.x) * 8;
  float v[8];
  *(float4*)&v[0] = *(const float4*)&src[off];
  *(float4*)&v[4] = *(const float4*)&src[off + 4];
  size_t o = (size_t)blockIdx.y*XN + off;
  split8_store(v, &d_x_hi[o], &d_x_lo[o]);
}

__global__ __launch_bounds__(256) void convw_kernel(
    const float* __restrict__ theta_w, const float* __restrict__ phi_w,
    const float* __restrict__ g_w)
{
  int i = (blockIdx.x*256 + threadIdx.x) * 8;
  int proj = i >> 15;
  int rem  = i & 32767;
  int d = rem >> 8, c8 = rem & 255;
  const float* w = proj == 0 ? theta_w : (proj == 1 ? phi_w : g_w);
  int cin = proj == 0 ? 257 : 256;
  float v[8];
  #pragma unroll
  for (int j = 0; j < 8; j++) v[j] = w[(size_t)d*cin + c8 + j];
  split8_store(v, &d_w_hi[i], &d_w_lo[i]);
}

// ======================= projection (theta/phi/g) — HMMA v2 ====================
#define PJ_SMEM 208896
__global__ __launch_bounds__(256, 1) void proj_hmma_kernel(
    const float* __restrict__ pre_l,  const float* __restrict__ pre_r,
    const float* __restrict__ query_l,const float* __restrict__ key_l,
    const float* __restrict__ query_r,const float* __restrict__ key_r,
    const float* __restrict__ theta_w,const float* __restrict__ theta_b,
    const float* __restrict__ phi_b,  const float* __restrict__ g_b)
{
  extern __shared__ char smem[];
  const uint32_t sb32 = smem_u32(smem);
  const int qt = blockIdx.x, b = blockIdx.y, z = blockIdx.z;
  const int side = z / 3, proj = z - side*3;
  const int tid = threadIdx.x, wid = tid >> 5, lid = tid & 31;
  const int q0 = qt * 64;

  const int srcidx = (proj == 0) ? side : (1 - side);
  const unsigned short* xh = d_x_hi + (size_t)srcidx*XN + (size_t)b*Cc*HW;
  const unsigned short* xl = d_x_lo + (size_t)srcidx*XN + (size_t)b*Cc*HW;
  const unsigned short* wh = d_w_hi + proj*128*256;
  const unsigned short* wl = d_w_lo + proj*128*256;

  #pragma unroll
  for (int t = 0; t < 16; t++) {
    int i = tid + t*256;
    int d = i >> 5, p = (i & 31) * 8;
    uint32_t o = (uint32_t)(d*264 + p) * 2;
    cpasync16(sb32 + 0u     + o, wh + (size_t)d*256 + p);
    cpasync16(sb32 + 67584u + o, wl + (size_t)d*256 + p);
  }
  auto issue_x = [&](int buf, int c0) {
    uint32_t XB = sb32 + 135168u + (uint32_t)buf*36864u;
    #pragma unroll
    for (int t = 0; t < 4; t++) {
      int i = tid + t*256;
      int r = i >> 3, p = (i & 7) * 8;
      uint32_t o = (uint32_t)(r*STB + p) * 2;
      size_t go = (size_t)(c0 + r)*HW + q0 + p;
      cpasync16(XB + o,          xh + go);
      cpasync16(XB + 18432u + o, xl + go);
    }
  };
  issue_x(0, 0);
  CP_COMMIT();
  issue_x(1, 128);
  CP_COMMIT();

  const int dm0  = wid * 16;
  const int arow = lid & 15;
  const int akh  = (lid & 16) ? 8 : 0;
  const int trow = lid & 15;
  const int tnh  = (lid & 16) ? 8 : 0;

  float acc[8][4];
  #pragma unroll
  for (int nf = 0; nf < 8; nf++)
    #pragma unroll
    for (int e = 0; e < 4; e++) acc[nf][e] = 0.f;

  #pragma unroll 1
  for (int ch = 0; ch < 2; ch++) {
    if (ch == 0) { CP_WAIT1(); } else { CP_WAIT0(); }
    __syncthreads();
    const int cofs = ch * 128;
    const uint32_t XH = sb32 + 135168u + (uint32_t)ch*36864u;
    const uint32_t XL = XH + 18432u;
    #pragma unroll
    for (int k16 = 0; k16 < 8; k16++) {
      uint32_t ah[4], al[4];
      ldm_x4(sb32 + 0u     + ((dm0 + arow)*264 + cofs + k16*16 + akh)*2, ah);
      ldm_x4(sb32 + 67584u + ((dm0 + arow)*264 + cofs + k16*16 + akh)*2, al);
      #pragma unroll
      for (int nq = 0; nq < 4; nq++) {
        uint32_t bh[4], bl[4];
        ldm_x4_t(XH + ((k16*16 + trow)*STB + nq*16 + tnh)*2, bh);
        hmma(acc[2*nq],   ah, bh);
        hmma(acc[2*nq+1], ah, bh + 2);
        hmma(acc[2*nq],   al, bh);
        hmma(acc[2*nq+1], al, bh + 2);
        ldm_x4_t(XL + ((k16*16 + trow)*STB + nq*16 + tnh)*2, bl);
        hmma(acc[2*nq],   ah, bl);
        hmma(acc[2*nq+1], ah, bl + 2);
      }
    }
  }

  const int sb = side*NB + b;
  const int d0 = dm0 + (lid >> 2), d1 = d0 + 8;
  unsigned short* dstH;
  unsigned short* dstL;
  const float* bias;
  if (proj == 0)      { dstH = d_th_hi; dstL = d_th_lo; bias = theta_b; }
  else if (proj == 1) { dstH = d_ph_hi; dstL = d_ph_lo; bias = phi_b; }
  else                { dstH = d_g_hi;  dstL = d_g_lo;  bias = g_b; }
  size_t r0 = ((size_t)sb*Dh + d0)*HW;
  size_t r1 = ((size_t)sb*Dh + d1)*HW;
  const float b0 = bias[d0], b1 = bias[d1];

  if (proj == 0) {
    const float* pre = side ? pre_r : pre_l;
    const float* qry = side ? query_r : query_l;
    const float wl0 = theta_w[(size_t)d0*257 + 256];
    const float wl1 = theta_w[(size_t)d1*257 + 256];
    const float* q0p = qry + ((size_t)b*Dh + d0)*HW;
    const float* q1p = qry + ((size_t)b*Dh + d1)*HW;
    #pragma unroll
    for (int nf = 0; nf < 8; nf++) {
      int q = q0 + nf*8 + (lid & 3)*2;
      float2 pr = *(const float2*)&pre[(size_t)b*HW + q];
      pr.x *= (1.0f/128.0f); pr.y *= (1.0f/128.0f);
      float2 qv0 = *(const float2*)&q0p[q];
      float2 qv1 = *(const float2*)&q1p[q];
      uint32_t h, l;
      packpair(acc[nf][0] + b0 + wl0*pr.x + qv0.x,
               acc[nf][1] + b0 + wl0*pr.y + qv0.y, h, l);
      *(uint32_t*)&dstH[r0 + q] = h;
      *(uint32_t*)&dstL[r0 + q] = l;
      packpair(acc[nf][2] + b1 + wl1*pr.x + qv1.x,
               acc[nf][3] + b1 + wl1*pr.y + qv1.y, h, l);
      *(uint32_t*)&dstH[r1 + q] = h;
      *(uint32_t*)&dstL[r1 + q] = l;
    }
  } else if (proj == 1) {
    const float* kf = side ? key_l : key_r;
    const float* k0p = kf + ((size_t)b*Dh + d0)*HW;
    const float* k1p = kf + ((size_t)b*Dh + d1)*HW;
    #pragma unroll
    for (int nf = 0; nf < 8; nf++) {
      int q = q0 + nf*8 + (lid & 3)*2;
      float2 kv0 = *(const float2*)&k0p[q];
      float2 kv1 = *(const float2*)&k1p[q];
      uint32_t h, l;
      packpair(acc[nf][0] + b0 + kv0.x, acc[nf][1] + b0 + kv0.y, h, l);
      *(uint32_t*)&dstH[r0 + q] = h;
      *(uint32_t*)&dstL[r0 + q] = l;
      packpair(acc[nf][2] + b1 + kv1.x, acc[nf][3] + b1 + kv1.y, h, l);
      *(uint32_t*)&dstH[r1 + q] = h;
      *(uint32_t*)&dstL[r1 + q] = l;
    }
  } else {
    #pragma unroll
    for (int nf = 0; nf < 8; nf++) {
      int q = q0 + nf*8 + (lid & 3)*2;
      uint32_t h, l;
      packpair(acc[nf][0] + b0, acc[nf][1] + b0, h, l);
      *(uint32_t*)&dstH[r0 + q] = h;
      *(uint32_t*)&dstL[r0 + q] = l;
      packpair(acc[nf][2] + b1, acc[nf][3] + b1, h, l);
      *(uint32_t*)&dstH[r1 + q] = h;
      *(uint32_t*)&dstL[r1 + q] = l;
    }
  }
}

// ======================= fused flash attention (HMMA, split-bf16) ===============
// grid (32 mtiles, KSPLIT, 8 sb), 256 threads, smem 217088B
// prefetch issued at loop TOP (full-iteration latency cover);
// exp/pack interleaved with PV MMA per kk group.
#define TH_HI_OFF 0u
#define TH_LO_OFF 34816u
#define BUF_OFF   69632u     // + buf*73728: phi hi, +18432 lo, +36864 g hi, +55296 g lo
#define FL_SMEM   217088

__global__ __launch_bounds__(256, 1) void flash_kernel()
{
  extern __shared__ char smem[];
  const uint32_t sb32 = smem_u32(smem);
  const int mtile = blockIdx.x, split = blockIdx.y, sb = blockIdx.z;
  const int tid = threadIdx.x, wid = tid >> 5, lid = tid & 31;
  const int q0 = mtile * 128;
  const int kbase0 = split * (HW / KSPLIT);

  const unsigned short* thH = d_th_hi + (size_t)sb*Dh*HW + q0;
  const unsigned short* thL = d_th_lo + (size_t)sb*Dh*HW + q0;
  const unsigned short* phH = d_ph_hi + (size_t)sb*Dh*HW;
  const unsigned short* phL = d_ph_lo + (size_t)sb*Dh*HW;
  const unsigned short* gH  = d_g_hi  + (size_t)sb*Dh*HW;
  const unsigned short* gL  = d_g_lo  + (size_t)sb*Dh*HW;

  // theta^T resident load: rows d 0..127, cols q0..q0+128
  #pragma unroll
  for (int t = 0; t < 8; t++) {
    int i = tid + t*256;
    int r = i >> 4, c8 = (i & 15) * 8;
    uint32_t o = (uint32_t)(r*ST + c8) * 2;
    size_t go = (size_t)r*HW + c8;
    *(uint4*)(smem + TH_HI_OFF + o) = *(const uint4*)&thH[go];
    *(uint4*)(smem + TH_LO_OFF + o) = *(const uint4*)&thL[go];
  }

  auto issue_chunk = [&](int buf, int kb) {
    uint32_t PB = sb32 + BUF_OFF + (uint32_t)buf*73728u;
    uint32_t GB = PB + 36864u;
    #pragma unroll
    for (int t = 0; t < 4; t++) {
      int i = tid + t*256;
      int r = i >> 3, p = (i & 7) * 8;
      uint32_t o = (uint32_t)(r*STB + p) * 2;
      size_t go = (size_t)r*HW + kb + p;
      cpasync16(PB + o,          phH + go);
      cpasync16(PB + 18432u + o, phL + go);
      cpasync16(GB + o,          gH + go);
      cpasync16(GB + 18432u + o, gL + go);
    }
  };

  issue_chunk(0, kbase0);
  CP_COMMIT();

  const int m0   = wid * 16;
  const int trow = lid & 15;
  const int tnh  = (lid & 16) ? 8 : 0;
  const int brow = (lid & 7) + ((lid & 16) ? 8 : 0);
  const int bkh  = (lid & 8) ? 8 : 0;
  const float wbase = (float)((lid & 3) * 2);

  float O[16][4];
  #pragma unroll
  for (int nf = 0; nf < 16; nf++)
    #pragma unroll
    for (int e = 0; e < 4; e++) O[nf][e] = 0.f;
  float lacc0 = 0.f, lacc1 = 0.f, cacc0 = 0.f, cacc1 = 0.f;

  #pragma unroll 1
  for (int it = 0; it < NITER; it++) {
    const int buf = it & 1;
    CP_WAIT0();
    __syncthreads();   // chunk `it` visible; all warps finished it-1's reads

    // ---- prefetch next chunk NOW (buf^1 free; full iteration covers latency) ----
    if (it + 1 < NITER) {
      issue_chunk(buf ^ 1, kbase0 + (it + 1)*BK);
      CP_COMMIT();
    }

    const uint32_t PH = sb32 + BUF_OFF + (uint32_t)buf*73728u;
    const uint32_t PL = PH + 18432u;
    const uint32_t GHs = PH + 36864u;
    const uint32_t GLs = GHs + 18432u;

    // ---- S = theta phi^T ----
    float acc[8][4];
    #pragma unroll
    for (int nf = 0; nf < 8; nf++)
      #pragma unroll
      for (int e = 0; e < 4; e++) acc[nf][e] = 0.f;

    #pragma unroll
    for (int k16 = 0; k16 < 8; k16++) {
      uint32_t rh[4], rl[4];
      ldm_x4_t(sb32 + TH_HI_OFF + ((k16*16 + trow)*ST + m0 + tnh)*2, rh);
      ldm_x4_t(sb32 + TH_LO_OFF + ((k16*16 + trow)*ST + m0 + tnh)*2, rl);
      uint32_t ah[4] = {rh[0], rh[2], rh[1], rh[3]};
      uint32_t al[4] = {rl[0], rl[2], rl[1], rl[3]};
      #pragma unroll
      for (int nb = 0; nb < 4; nb++) {
        uint32_t bh[4], bl[4];
        ldm_x4_t(PH + ((k16*16 + trow)*STB + nb*16 + tnh)*2, bh);
        hmma(acc[2*nb],   ah, bh);
        hmma(acc[2*nb+1], ah, bh + 2);
        hmma(acc[2*nb],   al, bh);
        hmma(acc[2*nb+1], al, bh + 2);
        ldm_x4_t(PL + ((k16*16 + trow)*STB + nb*16 + tnh)*2, bl);
        hmma(acc[2*nb],   ah, bl);
        hmma(acc[2*nb+1], ah, bl + 2);
      }
    }

    // ---- exp/pack interleaved with PV MMA per kk (shrinks tensor-idle bubble) ----
    const float wof = wbase + (buf ? 64.0f : 0.0f);
    #pragma unroll
    for (int kk = 0; kk < 4; kk++) {
      uint32_t a_h[4], a_l[4];
      #pragma unroll
      for (int j = 0; j < 2; j++) {
        const int nf = 2*kk + j;
        float w0 = wof + (float)(nf*8), w1 = w0 + 1.0f;
        float p0 = fexp(acc[nf][0]), p1 = fexp(acc[nf][1]);
        float p2 = fexp(acc[nf][2]), p3 = fexp(acc[nf][3]);
        lacc0 += p0 + p1;               lacc1 += p2 + p3;
        cacc0 += p0*w0 + p1*w1;         cacc1 += p2*w0 + p3*w1;
        packpair_t(p0, p1, a_h[2*j],   a_l[2*j]);
        packpair_t(p2, p3, a_h[2*j+1], a_l[2*j+1]);
      }
      #pragma unroll
      for (int nb = 0; nb < 8; nb++) {
        uint32_t bh[4], bl[4];
        ldm_x4(GHs + ((nb*16 + brow)*STB + kk*16 + bkh)*2, bh);
        hmma(O[2*nb],   a_h, bh);
        hmma(O[2*nb+1], a_h, bh + 2);
        hmma(O[2*nb],   a_l, bh);
        hmma(O[2*nb+1], a_l, bh + 2);
        ldm_x4(GLs + ((nb*16 + brow)*STB + kk*16 + bkh)*2, bl);
        hmma(O[2*nb],   a_h, bl);
        hmma(O[2*nb+1], a_h, bl + 2);
      }
    }
  }

  #pragma unroll
  for (int off = 1; off <= 2; off <<= 1) {
    lacc0 += __shfl_xor_sync(0xffffffffu, lacc0, off);
    lacc1 += __shfl_xor_sync(0xffffffffu, lacc1, off);
    cacc0 += __shfl_xor_sync(0xffffffffu, cacc0, off);
    cacc1 += __shfl_xor_sync(0xffffffffu, cacc1, off);
  }

  const int r0 = q0 + m0 + (lid >> 2);
  const int ssb = split*8 + sb;
  {
    float* o0 = d_op + ((size_t)ssb*HW + r0)*Dh + (lid & 3)*2;
    float* o1 = o0 + (size_t)8*Dh;
    #pragma unroll
    for (int nf = 0; nf < 16; nf++) {
      *(float2*)&o0[nf*8] = make_float2(O[nf][0], O[nf][1]);
      *(float2*)&o1[nf*8] = make_float2(O[nf][2], O[nf][3]);
    }
  }
  if ((lid & 3) == 0) {
    d_lcp[(size_t)ssb*HW + r0]     = make_float2(lacc0, cacc0);
    d_lcp[(size_t)ssb*HW + r0 + 8] = make_float2(lacc1, cacc1);
  }
}

// ======================= combine partials: normalize -> split bf16, index =======
__global__ __launch_bounds__(128) void combine_kernel(float* __restrict__ out)
{
  const int t = threadIdx.x, sb = blockIdx.y;
  const int q = blockIdx.x*2 + (t >> 6);
  const int d2 = (t & 63) * 2;
  float l = 0.f, c = 0.f;
  #pragma unroll
  for (int s = 0; s < KSPLIT; s++) {
    float2 lc = d_lcp[(size_t)(s*8 + sb)*HW + q];
    l += lc.x; c += lc.y;
  }
  float o0 = 0.f, o1 = 0.f;
  #pragma unroll
  for (int s = 0; s < KSPLIT; s++) {
    float2 v = *(const float2*)&d_op[((size_t)(s*8 + sb)*HW + q)*Dh + d2];
    o0 += v.x; o1 += v.y;
  }
  float inv = 1.0f / l;
  uint32_t h, lo;
  packpair(o0*inv, o1*inv, h, lo);
  *(uint32_t*)&d_af_hi[((size_t)sb*HW + q)*Dh + d2] = h;
  *(uint32_t*)&d_af_lo[((size_t)sb*HW + q)*Dh + d2] = lo;
  if ((t & 63) == 0)
    out[(size_t)2*NB*Cc*HW + (size_t)sb*HW + q] = (float)(q & 127) - c * inv;
}

// ======================= up-projection — HMMA (verified win) ====================
#define UP_SMEM 208896
__global__ __launch_bounds__(256, 1) void up_hmma_kernel(
    const float* __restrict__ up_w, const float* __restrict__ up_b)
{
  extern __shared__ char smem[];
  const uint32_t sb32 = smem_u32(smem);
  const int qtile = blockIdx.x, sb = blockIdx.y;
  const int tid = threadIdx.x, wid = tid >> 5, lid = tid & 31;
  const int q0 = qtile * 128;

  #pragma unroll
  for (int t = 0; t < 64; t++) {
    int i = tid + t*256;
    int cc = i >> 6, dd2 = (i & 63) * 2;
    float2 v = *(const float2*)&up_w[(size_t)cc*Dh + dd2];
    uint32_t h, l; packpair(v.x, v.y, h, l);
    uint32_t o = (uint32_t)(cc*ST + dd2) * 2;
    *(uint32_t*)(smem + 0u     + o) = h;
    *(uint32_t*)(smem + 69632u + o) = l;
  }
  {
    const unsigned short* bH = d_af_hi + ((size_t)sb*HW + q0)*Dh;
    const unsigned short* bL = d_af_lo + ((size_t)sb*HW + q0)*Dh;
    #pragma unroll
    for (int t = 0; t < 8; t++) {
      int i = tid + t*256;
      int r = i >> 4, c8 = (i & 15) * 8;
      uint32_t o = (uint32_t)(r*ST + c8) * 2;
      size_t go = (size_t)r*Dh + c8;
      *(uint4*)(smem + 139264u + o) = *(const uint4*)&bH[go];
      *(uint4*)(smem + 174080u + o) = *(const uint4*)&bL[go];
    }
  }
  __syncthreads();

  const int m0   = wid * 32;
  const int arow = lid & 15;
  const int akh  = (lid & 16) ? 8 : 0;
  const int brow = (lid & 7) + ((lid & 16) ? 8 : 0);
  const int bkh  = (lid & 8) ? 8 : 0;

  float acc[2][16][4];
  #pragma unroll
  for (int mf = 0; mf < 2; mf++)
    #pragma unroll
    for (int nf = 0; nf < 16; nf++)
      #pragma unroll
      for (int e = 0; e < 4; e++) acc[mf][nf][e] = 0.f;

  #pragma unroll
  for (int k16 = 0; k16 < 8; k16++) {
    uint32_t ah[2][4], al[2][4];
    #pragma unroll
    for (int mf = 0; mf < 2; mf++) {
      ldm_x4(sb32 + 0u     + ((m0 + mf*16 + arow)*ST + k16*16 + akh)*2, ah[mf]);
      ldm_x4(sb32 + 69632u + ((m0 + mf*16 + arow)*ST + k16*16 + akh)*2, al[mf]);
    }
    #pragma unroll
    for (int nb = 0; nb < 8; nb++) {
      uint32_t bh[4], bl[4];
      ldm_x4(sb32 + 139264u + ((nb*16 + brow)*ST + k16*16 + bkh)*2, bh);
      ldm_x4(sb32 + 174080u + ((nb*16 + brow)*ST + k16*16 + bkh)*2, bl);
      #pragma unroll
      for (int mf = 0; mf < 2; mf++) {
        hmma(acc[mf][2*nb],   ah[mf], bh);
        hmma(acc[mf][2*nb+1], ah[mf], bh + 2);
        hmma(acc[mf][2*nb],   al[mf], bh);
        hmma(acc[mf][2*nb+1], al[mf], bh + 2);
        hmma(acc[mf][2*nb],   ah[mf], bl);
        hmma(acc[mf][2*nb+1], ah[mf], bl + 2);
      }
    }
  }

  float* Yp = d_y + (size_t)sb*Cc*HW;
  #pragma unroll
  for (int mf = 0; mf < 2; mf++) {
    const int c0 = m0 + mf*16 + (lid >> 2);
    float bb0 = up_b[c0], bb1 = up_b[c0 + 8];
    #pragma unroll
    for (int nf = 0; nf < 16; nf++) {
      int qq = q0 + nf*8 + (lid & 3)*2;
      *(float2*)&Yp[(size_t)c0*HW + qq] =
          make_float2(acc[mf][nf][0] + bb0, acc[mf][nf][1] + bb0);
      *(float2*)&Yp[(size_t)(c0+8)*HW + qq] =
          make_float2(acc[mf][nf][2] + bb1, acc[mf][nf][3] + bb1);
    }
  }
}

// ======================= BN stats =======================
__global__ __launch_bounds__(256) void bn_stats_kernel()
{
  const int c = blockIdx.x, side = blockIdx.y;
  float s = 0.f, s2 = 0.f;
  for (int b = 0; b < NB; b++) {
    const float* p = d_y + (size_t)((side*NB + b)*Cc + c)*HW;
    for (int i = threadIdx.x; i < HW; i += 256) {
      float v = p[i];
      s += v; s2 += v*v;
    }
  }
  __shared__ float red[64];
  #pragma unroll
  for (int off = 16; off; off >>= 1) {
    s  += __shfl_down_sync(0xffffffffu, s,  off);
    s2 += __shfl_down_sync(0xffffffffu, s2, off);
  }
  int w = threadIdx.x >> 5;
  if ((threadIdx.x & 31) == 0) { red[w] = s; red[w + 32] = s2; }
  __syncthreads();
  if (threadIdx.x == 0) {
    float ts = 0.f, ts2 = 0.f;
    #pragma unroll
    for (int i = 0; i < 8; i++) { ts += red[i]; ts2 += red[i + 32]; }
    float mean = ts * (1.0f/16384.0f);
    float var  = ts2 * (1.0f/16384.0f) - mean*mean;
    d_bn[side*Cc + c] = make_float2(mean, rsqrtf(var + 1e-5f));
  }
}

// ======================= final: residual + BN apply =======================
__global__ __launch_bounds__(256) void final_kernel(
    const float* __restrict__ left, const float* __restrict__ right,
    const float* __restrict__ gamma, const float* __restrict__ beta,
    float* __restrict__ out)
{
  size_t i = ((size_t)blockIdx.x*256 + threadIdx.x) * 4;
  int q = (int)(i & 4095);
  size_t t = i >> 12;
  int c = (int)(t & 255); t >>= 8;
  int b = (int)(t & 3);
  int side = (int)(t >> 2);
  const float* x = side ? right : left;
  float4 xv = *(const float4*)&x[(((size_t)b*Cc + c) << 12) + q];
  float4 yv = *(const float4*)&d_y[i];
  float2 st = d_bn[side*Cc + c];
  float ga = gamma[c]*st.y;
  float be = beta[c] - ga*st.x;
  float4 r;
  r.x = xv.x + yv.x*ga + be;
  r.y = xv.y + yv.y*ga + be;
  r.z = xv.z + yv.z*ga + be;
  r.w = xv.w + yv.w*ga + be;
  *(float4*)&out[i] = r;
}

// ======================= launch =======================
extern "C" void kernel_launch(void* const* d_in, const int* in_sizes, int n_in,
                              void* d_out, int out_size)
{
  const float* left    = (const float*)d_in[0];
  const float* right   = (const float*)d_in[1];
  const float* pre_l   = (const float*)d_in[2];
  const float* pre_r   = (const float*)d_in[3];
  const float* query_l = (const float*)d_in[4];
  const float* key_l   = (const float*)d_in[5];
  const float* query_r = (const float*)d_in[6];
  const float* key_r   = (const float*)d_in[7];
  const float* theta_w = (const float*)d_in[8];
  const float* theta_b = (const float*)d_in[9];
  const float* phi_w   = (const float*)d_in[10];
  const float* phi_b   = (const float*)d_in[11];
  const float* g_w     = (const float*)d_in[12];
  const float* g_b     = (const float*)d_in[13];
  const float* up_w    = (const float*)d_in[14];
  const float* up_b    = (const float*)d_in[15];
  const float* bn_g    = (const float*)d_in[16];
  const float* bn_b    = (const float*)d_in[17];
  float* out = (float*)d_out;

  cudaFuncSetAttribute(proj_hmma_kernel, cudaFuncAttributeMaxDynamicSharedMemorySize, PJ_SMEM);
  cudaFuncSetAttribute(flash_kernel,     cudaFuncAttributeMaxDynamicSharedMemorySize, FL_SMEM);
  cudaFuncSetAttribute(up_hmma_kernel,   cudaFuncAttributeMaxDynamicSharedMemorySize, UP_SMEM);

  convx_kernel<<<dim3(2048, 2), 256>>>(left, right);
  convw_kernel<<<48, 256>>>(theta_w, phi_w, g_w);

  proj_hmma_kernel<<<dim3(64, NB, 6), 256, PJ_SMEM>>>(
      pre_l, pre_r, query_l, key_l, query_r, key_r,
      theta_w, theta_b, phi_b, g_b);

  flash_kernel<<<dim3(32, KSPLIT, 8), 256, FL_SMEM>>>();

  combine_kernel<<<dim3(HW/2, 8), 128>>>(out);

  up_hmma_kernel<<<dim3(32, 8), 256, UP_SMEM>>>(up_w, up_b);

  bn_stats_kernel<<<dim3(Cc, 2), 256>>>();

  final_kernel<<<dim3(2*NB*Cc*HW/4/256), 256>>>(left, right, bn_g, bn_b, out);
}

// round 15
// speedup vs baseline: 1.0071x; 1.0071x over previous
#include <cuda_runtime.h>
#include <cstdint>
#include <cstddef>

#define HW   4096
#define Dh   128
#define Cc   256
#define NB   4
#define ST   136   // theta smem row stride (bf16 elems)
#define STB  72    // phi/g/X chunk smem row stride (bf16 elems)
#define BK   64    // key chunk per flash iteration
#define KSPLIT 4
#define NITER (HW/KSPLIT/BK)   // 16

// ======================= helpers =======================
__device__ __forceinline__ uint32_t smem_u32(const void* p) {
  uint32_t a;
  asm("{ .reg .u64 t; cvta.to.shared.u64 t, %1; cvt.u32.u64 %0, t; }" : "=r"(a) : "l"(p));
  return a;
}
__device__ __forceinline__ void ldm_x4(uint32_t a, uint32_t* r) {
  asm volatile("ldmatrix.sync.aligned.m8n8.x4.shared.b16 {%0,%1,%2,%3}, [%4];"
               : "=r"(r[0]), "=r"(r[1]), "=r"(r[2]), "=r"(r[3]) : "r"(a));
}
__device__ __forceinline__ void ldm_x4_t(uint32_t a, uint32_t* r) {
  asm volatile("ldmatrix.sync.aligned.m8n8.x4.trans.shared.b16 {%0,%1,%2,%3}, [%4];"
               : "=r"(r[0]), "=r"(r[1]), "=r"(r[2]), "=r"(r[3]) : "r"(a));
}
__device__ __forceinline__ void hmma(float* d, const uint32_t* a, const uint32_t* b) {
  asm volatile("mma.sync.aligned.m16n8k16.row.col.f32.bf16.bf16.f32 "
               "{%0,%1,%2,%3}, {%4,%5,%6,%7}, {%8,%9}, {%0,%1,%2,%3};"
               : "+f"(d[0]), "+f"(d[1]), "+f"(d[2]), "+f"(d[3])
               : "r"(a[0]), "r"(a[1]), "r"(a[2]), "r"(a[3]), "r"(b[0]), "r"(b[1]));
}
__device__ __forceinline__ void cpasync16(uint32_t dst, const void* src) {
  asm volatile("cp.async.cg.shared.global [%0], [%1], 16;" :: "r"(dst), "l"(src));
}
#define CP_COMMIT() asm volatile("cp.async.commit_group;" ::: "memory")
#define CP_WAIT0()  asm volatile("cp.async.wait_group 0;" ::: "memory")
#define CP_WAIT1()  asm volatile("cp.async.wait_group 1;" ::: "memory")

// bf16 RN-even bits (kept in HIGH half, low 16 zero) — pure int ops, no CVT
__device__ __forceinline__ uint32_t hbits(float x) {
  uint32_t u = __float_as_uint(x);
  return (u + 0x7FFFu + ((u >> 16) & 1u)) & 0xFFFF0000u;
}
// fast exp on FMA/ALU pipes (no MUFU)
__device__ __forceinline__ float fexp(float x) {
  float t = x * 1.4426950408889634f;
  float r = t + 12582912.0f;
  int   n = __float_as_int(r) - 0x4B400000;
  float f = t - (r - 12582912.0f);
  float p = 1.540353e-4f;
  p = fmaf(p, f, 1.3333558e-3f);
  p = fmaf(p, f, 9.6181291e-3f);
  p = fmaf(p, f, 5.5504109e-2f);
  p = fmaf(p, f, 2.4022651e-1f);
  p = fmaf(p, f, 6.9314718e-1f);
  p = fmaf(p, f, 1.0f);
  n = max(n, -126);
  return p * __int_as_float((n + 127) << 23);
}
// RN pack (x,y) -> bf16x2 hi + residual bf16x2 lo (cold paths)
__device__ __forceinline__ void packpair(float x, float y, uint32_t& h, uint32_t& l) {
  uint32_t hx = hbits(x), hy = hbits(y);
  h = __byte_perm(hx, hy, 0x7632);
  float lx = x - __uint_as_float(hx), ly = y - __uint_as_float(hy);
  l = __byte_perm(hbits(lx), hbits(ly), 0x7632);
}
// TRUNC pack (hot PV loop; valid when dropped lo*lo term has random sign)
__device__ __forceinline__ void packpair_t(float x, float y, uint32_t& h, uint32_t& l) {
  uint32_t ux = __float_as_uint(x), uy = __float_as_uint(y);
  h = __byte_perm(ux, uy, 0x7632);
  float lx = x - __uint_as_float(ux & 0xFFFF0000u);
  float ly = y - __uint_as_float(uy & 0xFFFF0000u);
  l = __byte_perm(__float_as_uint(lx), __float_as_uint(ly), 0x7632);
}
// split 8 floats -> bf16 hi/lo packed stores (RN)
__device__ __forceinline__ void split8_store(const float* v, unsigned short* hiP,
                                             unsigned short* loP) {
  uint32_t hw[4], lw[4];
  #pragma unroll
  for (int i = 0; i < 4; i++) {
    uint32_t h0 = hbits(v[2*i]), h1 = hbits(v[2*i+1]);
    hw[i] = __byte_perm(h0, h1, 0x7632);
    float l0 = v[2*i]   - __uint_as_float(h0);
    float l1 = v[2*i+1] - __uint_as_float(h1);
    lw[i] = __byte_perm(hbits(l0), hbits(l1), 0x7632);
  }
  *(uint4*)hiP = make_uint4(hw[0], hw[1], hw[2], hw[3]);
  *(uint4*)loP = make_uint4(lw[0], lw[1], lw[2], lw[3]);
}

// ---------------- scratch (device globals, no allocation) ----------------
#define XN ((size_t)NB*Cc*HW)   // 4194304 elems per source tensor
__device__ unsigned short d_x_hi[2*XN];              // split left/right [src][b][c][hw]
__device__ unsigned short d_x_lo[2*XN];
__device__ unsigned short d_w_hi[3*128*256];         // split weights [proj][d][c]
__device__ unsigned short d_w_lo[3*128*256];
__device__ unsigned short d_th_hi[(size_t)8*Dh*HW];  // theta^T [sb][d][q]
__device__ unsigned short d_th_lo[(size_t)8*Dh*HW];
__device__ unsigned short d_ph_hi[(size_t)8*Dh*HW];  // phi^T   [sb][d][key]
__device__ unsigned short d_ph_lo[(size_t)8*Dh*HW];
__device__ unsigned short d_g_hi [(size_t)8*Dh*HW];  // g^T     [sb][d][k]
__device__ unsigned short d_g_lo [(size_t)8*Dh*HW];
__device__ float  d_op [(size_t)KSPLIT*8*HW*Dh];     // unnormalized O partials
__device__ float2 d_lcp[(size_t)KSPLIT*8*HW];        // (l, c) partials
__device__ float  d_y    [(size_t)8*Cc*HW];
__device__ float2 d_bn   [2*Cc];

// ======================= input conversion kernels =======================
__global__ __launch_bounds__(256) void convx_kernel(
    const float* __restrict__ left, const float* __restrict__ right)
{
  const float* src = blockIdx.y ? right : left;
  size_t off = ((size_t)blockIdx.x*256 + threadIdx.x) * 8;
  float v[8];
  *(float4*)&v[0] = *(const float4*)&src[off];
  *(float4*)&v[4] = *(const float4*)&src[off + 4];
  size_t o = (size_t)blockIdx.y*XN + off;
  split8_store(v, &d_x_hi[o], &d_x_lo[o]);
}

__global__ __launch_bounds__(256) void convw_kernel(
    const float* __restrict__ theta_w, const float* __restrict__ phi_w,
    const float* __restrict__ g_w)
{
  int i = (blockIdx.x*256 + threadIdx.x) * 8;
  int proj = i >> 15;
  int rem  = i & 32767;
  int d = rem >> 8, c8 = rem & 255;
  const float* w = proj == 0 ? theta_w : (proj == 1 ? phi_w : g_w);
  int cin = proj == 0 ? 257 : 256;
  float v[8];
  #pragma unroll
  for (int j = 0; j < 8; j++) v[j] = w[(size_t)d*cin + c8 + j];
  split8_store(v, &d_w_hi[i], &d_w_lo[i]);
}

// ======================= projection (theta/phi/g) — HMMA v2 ====================
#define PJ_SMEM 208896
__global__ __launch_bounds__(256, 1) void proj_hmma_kernel(
    const float* __restrict__ pre_l,  const float* __restrict__ pre_r,
    const float* __restrict__ query_l,const float* __restrict__ key_l,
    const float* __restrict__ query_r,const float* __restrict__ key_r,
    const float* __restrict__ theta_w,const float* __restrict__ theta_b,
    const float* __restrict__ phi_b,  const float* __restrict__ g_b)
{
  extern __shared__ char smem[];
  const uint32_t sb32 = smem_u32(smem);
  const int qt = blockIdx.x, b = blockIdx.y, z = blockIdx.z;
  const int side = z / 3, proj = z - side*3;
  const int tid = threadIdx.x, wid = tid >> 5, lid = tid & 31;
  const int q0 = qt * 64;

  const int srcidx = (proj == 0) ? side : (1 - side);
  const unsigned short* xh = d_x_hi + (size_t)srcidx*XN + (size_t)b*Cc*HW;
  const unsigned short* xl = d_x_lo + (size_t)srcidx*XN + (size_t)b*Cc*HW;
  const unsigned short* wh = d_w_hi + proj*128*256;
  const unsigned short* wl = d_w_lo + proj*128*256;

  #pragma unroll
  for (int t = 0; t < 16; t++) {
    int i = tid + t*256;
    int d = i >> 5, p = (i & 31) * 8;
    uint32_t o = (uint32_t)(d*264 + p) * 2;
    cpasync16(sb32 + 0u     + o, wh + (size_t)d*256 + p);
    cpasync16(sb32 + 67584u + o, wl + (size_t)d*256 + p);
  }
  auto issue_x = [&](int buf, int c0) {
    uint32_t XB = sb32 + 135168u + (uint32_t)buf*36864u;
    #pragma unroll
    for (int t = 0; t < 4; t++) {
      int i = tid + t*256;
      int r = i >> 3, p = (i & 7) * 8;
      uint32_t o = (uint32_t)(r*STB + p) * 2;
      size_t go = (size_t)(c0 + r)*HW + q0 + p;
      cpasync16(XB + o,          xh + go);
      cpasync16(XB + 18432u + o, xl + go);
    }
  };
  issue_x(0, 0);
  CP_COMMIT();
  issue_x(1, 128);
  CP_COMMIT();

  const int dm0  = wid * 16;
  const int arow = lid & 15;
  const int akh  = (lid & 16) ? 8 : 0;
  const int trow = lid & 15;
  const int tnh  = (lid & 16) ? 8 : 0;

  float acc[8][4];
  #pragma unroll
  for (int nf = 0; nf < 8; nf++)
    #pragma unroll
    for (int e = 0; e < 4; e++) acc[nf][e] = 0.f;

  #pragma unroll 1
  for (int ch = 0; ch < 2; ch++) {
    if (ch == 0) { CP_WAIT1(); } else { CP_WAIT0(); }
    __syncthreads();
    const int cofs = ch * 128;
    const uint32_t XH = sb32 + 135168u + (uint32_t)ch*36864u;
    const uint32_t XL = XH + 18432u;
    #pragma unroll
    for (int k16 = 0; k16 < 8; k16++) {
      uint32_t ah[4], al[4];
      ldm_x4(sb32 + 0u     + ((dm0 + arow)*264 + cofs + k16*16 + akh)*2, ah);
      ldm_x4(sb32 + 67584u + ((dm0 + arow)*264 + cofs + k16*16 + akh)*2, al);
      #pragma unroll
      for (int nq = 0; nq < 4; nq++) {
        uint32_t bh[4], bl[4];
        ldm_x4_t(XH + ((k16*16 + trow)*STB + nq*16 + tnh)*2, bh);
        hmma(acc[2*nq],   ah, bh);
        hmma(acc[2*nq+1], ah, bh + 2);
        hmma(acc[2*nq],   al, bh);
        hmma(acc[2*nq+1], al, bh + 2);
        ldm_x4_t(XL + ((k16*16 + trow)*STB + nq*16 + tnh)*2, bl);
        hmma(acc[2*nq],   ah, bl);
        hmma(acc[2*nq+1], ah, bl + 2);
      }
    }
  }

  const int sb = side*NB + b;
  const int d0 = dm0 + (lid >> 2), d1 = d0 + 8;
  unsigned short* dstH;
  unsigned short* dstL;
  const float* bias;
  if (proj == 0)      { dstH = d_th_hi; dstL = d_th_lo; bias = theta_b; }
  else if (proj == 1) { dstH = d_ph_hi; dstL = d_ph_lo; bias = phi_b; }
  else                { dstH = d_g_hi;  dstL = d_g_lo;  bias = g_b; }
  size_t r0 = ((size_t)sb*Dh + d0)*HW;
  size_t r1 = ((size_t)sb*Dh + d1)*HW;
  const float b0 = bias[d0], b1 = bias[d1];

  if (proj == 0) {
    const float* pre = side ? pre_r : pre_l;
    const float* qry = side ? query_r : query_l;
    const float wl0 = theta_w[(size_t)d0*257 + 256];
    const float wl1 = theta_w[(size_t)d1*257 + 256];
    const float* q0p = qry + ((size_t)b*Dh + d0)*HW;
    const float* q1p = qry + ((size_t)b*Dh + d1)*HW;
    #pragma unroll
    for (int nf = 0; nf < 8; nf++) {
      int q = q0 + nf*8 + (lid & 3)*2;
      float2 pr = *(const float2*)&pre[(size_t)b*HW + q];
      pr.x *= (1.0f/128.0f); pr.y *= (1.0f/128.0f);
      float2 qv0 = *(const float2*)&q0p[q];
      float2 qv1 = *(const float2*)&q1p[q];
      uint32_t h, l;
      packpair(acc[nf][0] + b0 + wl0*pr.x + qv0.x,
               acc[nf][1] + b0 + wl0*pr.y + qv0.y, h, l);
      *(uint32_t*)&dstH[r0 + q] = h;
      *(uint32_t*)&dstL[r0 + q] = l;
      packpair(acc[nf][2] + b1 + wl1*pr.x + qv1.x,
               acc[nf][3] + b1 + wl1*pr.y + qv1.y, h, l);
      *(uint32_t*)&dstH[r1 + q] = h;
      *(uint32_t*)&dstL[r1 + q] = l;
    }
  } else if (proj == 1) {
    const float* kf = side ? key_l : key_r;
    const float* k0p = kf + ((size_t)b*Dh + d0)*HW;
    const float* k1p = kf + ((size_t)b*Dh + d1)*HW;
    #pragma unroll
    for (int nf = 0; nf < 8; nf++) {
      int q = q0 + nf*8 + (lid & 3)*2;
      float2 kv0 = *(const float2*)&k0p[q];
      float2 kv1 = *(const float2*)&k1p[q];
      uint32_t h, l;
      packpair(acc[nf][0] + b0 + kv0.x, acc[nf][1] + b0 + kv0.y, h, l);
      *(uint32_t*)&dstH[r0 + q] = h;
      *(uint32_t*)&dstL[r0 + q] = l;
      packpair(acc[nf][2] + b1 + kv1.x, acc[nf][3] + b1 + kv1.y, h, l);
      *(uint32_t*)&dstH[r1 + q] = h;
      *(uint32_t*)&dstL[r1 + q] = l;
    }
  } else {
    #pragma unroll
    for (int nf = 0; nf < 8; nf++) {
      int q = q0 + nf*8 + (lid & 3)*2;
      uint32_t h, l;
      packpair(acc[nf][0] + b0, acc[nf][1] + b0, h, l);
      *(uint32_t*)&dstH[r0 + q] = h;
      *(uint32_t*)&dstL[r0 + q] = l;
      packpair(acc[nf][2] + b1, acc[nf][3] + b1, h, l);
      *(uint32_t*)&dstH[r1 + q] = h;
      *(uint32_t*)&dstL[r1 + q] = l;
    }
  }
}

// ======================= fused flash attention (HMMA, split-bf16) ===============
// R13 structure (mid-iteration prefetch, monolithic exp epilogue) +
// pairwise-nb HMMA interleave: same-accumulator distance 2 -> 4.
#define TH_HI_OFF 0u
#define TH_LO_OFF 34816u
#define BUF_OFF   69632u     // + buf*73728: phi hi, +18432 lo, +36864 g hi, +55296 g lo
#define FL_SMEM   217088

__global__ __launch_bounds__(256, 1) void flash_kernel()
{
  extern __shared__ char smem[];
  const uint32_t sb32 = smem_u32(smem);
  const int mtile = blockIdx.x, split = blockIdx.y, sb = blockIdx.z;
  const int tid = threadIdx.x, wid = tid >> 5, lid = tid & 31;
  const int q0 = mtile * 128;
  const int kbase0 = split * (HW / KSPLIT);

  const unsigned short* thH = d_th_hi + (size_t)sb*Dh*HW + q0;
  const unsigned short* thL = d_th_lo + (size_t)sb*Dh*HW + q0;
  const unsigned short* phH = d_ph_hi + (size_t)sb*Dh*HW;
  const unsigned short* phL = d_ph_lo + (size_t)sb*Dh*HW;
  const unsigned short* gH  = d_g_hi  + (size_t)sb*Dh*HW;
  const unsigned short* gL  = d_g_lo  + (size_t)sb*Dh*HW;

  #pragma unroll
  for (int t = 0; t < 8; t++) {
    int i = tid + t*256;
    int r = i >> 4, c8 = (i & 15) * 8;
    uint32_t o = (uint32_t)(r*ST + c8) * 2;
    size_t go = (size_t)r*HW + c8;
    *(uint4*)(smem + TH_HI_OFF + o) = *(const uint4*)&thH[go];
    *(uint4*)(smem + TH_LO_OFF + o) = *(const uint4*)&thL[go];
  }

  auto issue_chunk = [&](int buf, int kb) {
    uint32_t PB = sb32 + BUF_OFF + (uint32_t)buf*73728u;
    uint32_t GB = PB + 36864u;
    #pragma unroll
    for (int t = 0; t < 4; t++) {
      int i = tid + t*256;
      int r = i >> 3, p = (i & 7) * 8;
      uint32_t o = (uint32_t)(r*STB + p) * 2;
      size_t go = (size_t)r*HW + kb + p;
      cpasync16(PB + o,          phH + go);
      cpasync16(PB + 18432u + o, phL + go);
      cpasync16(GB + o,          gH + go);
      cpasync16(GB + 18432u + o, gL + go);
    }
  };

  issue_chunk(0, kbase0);
  CP_COMMIT();

  const int m0   = wid * 16;
  const int trow = lid & 15;
  const int tnh  = (lid & 16) ? 8 : 0;
  const int brow = (lid & 7) + ((lid & 16) ? 8 : 0);
  const int bkh  = (lid & 8) ? 8 : 0;
  const float wbase = (float)((lid & 3) * 2);

  float O[16][4];
  #pragma unroll
  for (int nf = 0; nf < 16; nf++)
    #pragma unroll
    for (int e = 0; e < 4; e++) O[nf][e] = 0.f;
  float lacc0 = 0.f, lacc1 = 0.f, cacc0 = 0.f, cacc1 = 0.f;

  #pragma unroll 1
  for (int it = 0; it < NITER; it++) {
    const int buf = it & 1;
    CP_WAIT0();
    __syncthreads();   // chunk `it` visible; all warps finished it-1's reads

    const uint32_t PH = sb32 + BUF_OFF + (uint32_t)buf*73728u;
    const uint32_t PL = PH + 18432u;
    const uint32_t GHs = PH + 36864u;
    const uint32_t GLs = GHs + 18432u;

    // ---- S = theta phi^T (nb processed in pairs: acc distance 2 -> 4) ----
    float acc[8][4];
    #pragma unroll
    for (int nf = 0; nf < 8; nf++)
      #pragma unroll
      for (int e = 0; e < 4; e++) acc[nf][e] = 0.f;

    #pragma unroll
    for (int k16 = 0; k16 < 8; k16++) {
      uint32_t rh[4], rl[4];
      ldm_x4_t(sb32 + TH_HI_OFF + ((k16*16 + trow)*ST + m0 + tnh)*2, rh);
      ldm_x4_t(sb32 + TH_LO_OFF + ((k16*16 + trow)*ST + m0 + tnh)*2, rl);
      uint32_t ah[4] = {rh[0], rh[2], rh[1], rh[3]};
      uint32_t al[4] = {rl[0], rl[2], rl[1], rl[3]};
      #pragma unroll
      for (int p = 0; p < 2; p++) {
        const int nb0 = 2*p, nb1 = 2*p + 1;
        uint32_t bh0[4], bh1[4], bl0[4], bl1[4];
        ldm_x4_t(PH + ((k16*16 + trow)*STB + nb0*16 + tnh)*2, bh0);
        ldm_x4_t(PH + ((k16*16 + trow)*STB + nb1*16 + tnh)*2, bh1);
        hmma(acc[2*nb0],   ah, bh0);
        hmma(acc[2*nb0+1], ah, bh0 + 2);
        hmma(acc[2*nb1],   ah, bh1);
        hmma(acc[2*nb1+1], ah, bh1 + 2);
        hmma(acc[2*nb0],   al, bh0);
        hmma(acc[2*nb0+1], al, bh0 + 2);
        hmma(acc[2*nb1],   al, bh1);
        hmma(acc[2*nb1+1], al, bh1 + 2);
        ldm_x4_t(PL + ((k16*16 + trow)*STB + nb0*16 + tnh)*2, bl0);
        ldm_x4_t(PL + ((k16*16 + trow)*STB + nb1*16 + tnh)*2, bl1);
        hmma(acc[2*nb0],   ah, bl0);
        hmma(acc[2*nb0+1], ah, bl0 + 2);
        hmma(acc[2*nb1],   ah, bl1);
        hmma(acc[2*nb1+1], ah, bl1 + 2);
      }
    }

    // ---- exp + l/c row sums ----
    const float wof = wbase + (buf ? 64.0f : 0.0f);
    #pragma unroll
    for (int nf = 0; nf < 8; nf++) {
      float w0 = wof + (float)(nf*8), w1 = w0 + 1.0f;
      float p0 = fexp(acc[nf][0]), p1 = fexp(acc[nf][1]);
      float p2 = fexp(acc[nf][2]), p3 = fexp(acc[nf][3]);
      acc[nf][0] = p0; acc[nf][1] = p1; acc[nf][2] = p2; acc[nf][3] = p3;
      lacc0 += p0 + p1;               lacc1 += p2 + p3;
      cacc0 += p0*w0 + p1*w1;         cacc1 += p2*w0 + p3*w1;
    }

    // ---- prefetch next chunk (mid-iteration placement — R13-verified) ----
    if (it + 1 < NITER) {
      issue_chunk(buf ^ 1, kbase0 + (it + 1)*BK);
      CP_COMMIT();
    }

    // ---- O += P g (trunc split; nb processed in pairs: acc distance 4) ----
    #pragma unroll
    for (int kk = 0; kk < 4; kk++) {
      uint32_t a_h[4], a_l[4];
      packpair_t(acc[2*kk][0],   acc[2*kk][1],   a_h[0], a_l[0]);
      packpair_t(acc[2*kk][2],   acc[2*kk][3],   a_h[1], a_l[1]);
      packpair_t(acc[2*kk+1][0], acc[2*kk+1][1], a_h[2], a_l[2]);
      packpair_t(acc[2*kk+1][2], acc[2*kk+1][3], a_h[3], a_l[3]);
      #pragma unroll
      for (int p = 0; p < 4; p++) {
        const int nb0 = 2*p, nb1 = 2*p + 1;
        uint32_t bh0[4], bh1[4], bl0[4], bl1[4];
        ldm_x4(GHs + ((nb0*16 + brow)*STB + kk*16 + bkh)*2, bh0);
        ldm_x4(GHs + ((nb1*16 + brow)*STB + kk*16 + bkh)*2, bh1);
        hmma(O[2*nb0],   a_h, bh0);
        hmma(O[2*nb0+1], a_h, bh0 + 2);
        hmma(O[2*nb1],   a_h, bh1);
        hmma(O[2*nb1+1], a_h, bh1 + 2);
        hmma(O[2*nb0],   a_l, bh0);
        hmma(O[2*nb0+1], a_l, bh0 + 2);
        hmma(O[2*nb1],   a_l, bh1);
        hmma(O[2*nb1+1], a_l, bh1 + 2);
        ldm_x4(GLs + ((nb0*16 + brow)*STB + kk*16 + bkh)*2, bl0);
        ldm_x4(GLs + ((nb1*16 + brow)*STB + kk*16 + bkh)*2, bl1);
        hmma(O[2*nb0],   a_h, bl0);
        hmma(O[2*nb0+1], a_h, bl0 + 2);
        hmma(O[2*nb1],   a_h, bl1);
        hmma(O[2*nb1+1], a_h, bl1 + 2);
      }
    }
  }

  #pragma unroll
  for (int off = 1; off <= 2; off <<= 1) {
    lacc0 += __shfl_xor_sync(0xffffffffu, lacc0, off);
    lacc1 += __shfl_xor_sync(0xffffffffu, lacc1, off);
    cacc0 += __shfl_xor_sync(0xffffffffu, cacc0, off);
    cacc1 += __shfl_xor_sync(0xffffffffu, cacc1, off);
  }

  const int r0 = q0 + m0 + (lid >> 2);
  const int ssb = split*8 + sb;
  {
    float* o0 = d_op + ((size_t)ssb*HW + r0)*Dh + (lid & 3)*2;
    float* o1 = o0 + (size_t)8*Dh;
    #pragma unroll
    for (int nf = 0; nf < 16; nf++) {
      *(float2*)&o0[nf*8] = make_float2(O[nf][0], O[nf][1]);
      *(float2*)&o1[nf*8] = make_float2(O[nf][2], O[nf][3]);
    }
  }
  if ((lid & 3) == 0) {
    d_lcp[(size_t)ssb*HW + r0]     = make_float2(lacc0, cacc0);
    d_lcp[(size_t)ssb*HW + r0 + 8] = make_float2(lacc1, cacc1);
  }
}

// ======================= up-projection — HMMA, combine FUSED into prologue ======
// grid (32 qtiles, 8 sb), 256 threads, smem 208896B
// prologue: sum d_op partials + d_lcp, normalize, RN-split directly into smem B
// tiles; write index output. Then GEMM y = up_w @ after^T as before.
#define UP_SMEM 208896
__global__ __launch_bounds__(256, 1) void up_hmma_kernel(
    const float* __restrict__ up_w, const float* __restrict__ up_b,
    float* __restrict__ out)
{
  extern __shared__ char smem[];
  const uint32_t sb32 = smem_u32(smem);
  const int qtile = blockIdx.x, sb = blockIdx.y;
  const int tid = threadIdx.x, wid = tid >> 5, lid = tid & 31;
  const int q0 = qtile * 128;

  // convert A = up_w [256 c][128 d]
  #pragma unroll
  for (int t = 0; t < 64; t++) {
    int i = tid + t*256;
    int cc = i >> 6, dd2 = (i & 63) * 2;
    float2 v = *(const float2*)&up_w[(size_t)cc*Dh + dd2];
    uint32_t h, l; packpair(v.x, v.y, h, l);
    uint32_t o = (uint32_t)(cc*ST + dd2) * 2;
    *(uint32_t*)(smem + 0u     + o) = h;
    *(uint32_t*)(smem + 69632u + o) = l;
  }
  // fused combine: B tile = normalize(sum_s d_op) split-bf16; index out
  #pragma unroll
  for (int t = 0; t < 8; t++) {
    int i = tid + t*256;
    int r = i >> 4, c8 = (i & 15) * 8;
    const int q = q0 + r;
    float l = 0.f, c = 0.f;
    #pragma unroll
    for (int s = 0; s < KSPLIT; s++) {
      float2 lc = d_lcp[(size_t)(s*8 + sb)*HW + q];
      l += lc.x; c += lc.y;
    }
    float inv = 1.0f / l;
    float v[8];
    #pragma unroll
    for (int j = 0; j < 8; j++) v[j] = 0.f;
    #pragma unroll
    for (int s = 0; s < KSPLIT; s++) {
      const float* op = d_op + ((size_t)(s*8 + sb)*HW + q)*Dh + c8;
      float4 a = *(const float4*)&op[0];
      float4 bq = *(const float4*)&op[4];
      v[0] += a.x;  v[1] += a.y;  v[2] += a.z;  v[3] += a.w;
      v[4] += bq.x; v[5] += bq.y; v[6] += bq.z; v[7] += bq.w;
    }
    uint32_t hw[4], lw[4];
    #pragma unroll
    for (int j = 0; j < 4; j++) {
      float x = v[2*j]*inv, y = v[2*j+1]*inv;
      packpair(x, y, hw[j], lw[j]);
    }
    uint32_t o = (uint32_t)(r*ST + c8) * 2;
    *(uint4*)(smem + 139264u + o) = make_uint4(hw[0], hw[1], hw[2], hw[3]);
    *(uint4*)(smem + 174080u + o) = make_uint4(lw[0], lw[1], lw[2], lw[3]);
    if (c8 == 0)
      out[(size_t)2*NB*Cc*HW + (size_t)sb*HW + q] = (float)(q & 127) - c * inv;
  }
  __syncthreads();

  const int m0   = wid * 32;
  const int arow = lid & 15;
  const int akh  = (lid & 16) ? 8 : 0;
  const int brow = (lid & 7) + ((lid & 16) ? 8 : 0);
  const int bkh  = (lid & 8) ? 8 : 0;

  float acc[2][16][4];
  #pragma unroll
  for (int mf = 0; mf < 2; mf++)
    #pragma unroll
    for (int nf = 0; nf < 16; nf++)
      #pragma unroll
      for (int e = 0; e < 4; e++) acc[mf][nf][e] = 0.f;

  #pragma unroll
  for (int k16 = 0; k16 < 8; k16++) {
    uint32_t ah[2][4], al[2][4];
    #pragma unroll
    for (int mf = 0; mf < 2; mf++) {
      ldm_x4(sb32 + 0u     + ((m0 + mf*16 + arow)*ST + k16*16 + akh)*2, ah[mf]);
      ldm_x4(sb32 + 69632u + ((m0 + mf*16 + arow)*ST + k16*16 + akh)*2, al[mf]);
    }
    #pragma unroll
    for (int nb = 0; nb < 8; nb++) {
      uint32_t bh[4], bl[4];
      ldm_x4(sb32 + 139264u + ((nb*16 + brow)*ST + k16*16 + bkh)*2, bh);
      ldm_x4(sb32 + 174080u + ((nb*16 + brow)*ST + k16*16 + bkh)*2, bl);
      #pragma unroll
      for (int mf = 0; mf < 2; mf++) {
        hmma(acc[mf][2*nb],   ah[mf], bh);
        hmma(acc[mf][2*nb+1], ah[mf], bh + 2);
        hmma(acc[mf][2*nb],   al[mf], bh);
        hmma(acc[mf][2*nb+1], al[mf], bh + 2);
        hmma(acc[mf][2*nb],   ah[mf], bl);
        hmma(acc[mf][2*nb+1], ah[mf], bl + 2);
      }
    }
  }

  float* Yp = d_y + (size_t)sb*Cc*HW;
  #pragma unroll
  for (int mf = 0; mf < 2; mf++) {
    const int c0 = m0 + mf*16 + (lid >> 2);
    float bb0 = up_b[c0], bb1 = up_b[c0 + 8];
    #pragma unroll
    for (int nf = 0; nf < 16; nf++) {
      int qq = q0 + nf*8 + (lid & 3)*2;
      *(float2*)&Yp[(size_t)c0*HW + qq] =
          make_float2(acc[mf][nf][0] + bb0, acc[mf][nf][1] + bb0);
      *(float2*)&Yp[(size_t)(c0+8)*HW + qq] =
          make_float2(acc[mf][nf][2] + bb1, acc[mf][nf][3] + bb1);
    }
  }
}

// ======================= BN stats =======================
__global__ __launch_bounds__(256) void bn_stats_kernel()
{
  const int c = blockIdx.x, side = blockIdx.y;
  float s = 0.f, s2 = 0.f;
  for (int b = 0; b < NB; b++) {
    const float* p = d_y + (size_t)((side*NB + b)*Cc + c)*HW;
    for (int i = threadIdx.x; i < HW; i += 256) {
      float v = p[i];
      s += v; s2 += v*v;
    }
  }
  __shared__ float red[64];
  #pragma unroll
  for (int off = 16; off; off >>= 1) {
    s  += __shfl_down_sync(0xffffffffu, s,  off);
    s2 += __shfl_down_sync(0xffffffffu, s2, off);
  }
  int w = threadIdx.x >> 5;
  if ((threadIdx.x & 31) == 0) { red[w] = s; red[w + 32] = s2; }
  __syncthreads();
  if (threadIdx.x == 0) {
    float ts = 0.f, ts2 = 0.f;
    #pragma unroll
    for (int i = 0; i < 8; i++) { ts += red[i]; ts2 += red[i + 32]; }
    float mean = ts * (1.0f/16384.0f);
    float var  = ts2 * (1.0f/16384.0f) - mean*mean;
    d_bn[side*Cc + c] = make_float2(mean, rsqrtf(var + 1e-5f));
  }
}

// ======================= final: residual + BN apply =======================
__global__ __launch_bounds__(256) void final_kernel(
    const float* __restrict__ left, const float* __restrict__ right,
    const float* __restrict__ gamma, const float* __restrict__ beta,
    float* __restrict__ out)
{
  size_t i = ((size_t)blockIdx.x*256 + threadIdx.x) * 4;
  int q = (int)(i & 4095);
  size_t t = i >> 12;
  int c = (int)(t & 255); t >>= 8;
  int b = (int)(t & 3);
  int side = (int)(t >> 2);
  const float* x = side ? right : left;
  float4 xv = *(const float4*)&x[(((size_t)b*Cc + c) << 12) + q];
  float4 yv = *(const float4*)&d_y[i];
  float2 st = d_bn[side*Cc + c];
  float ga = gamma[c]*st.y;
  float be = beta[c] - ga*st.x;
  float4 r;
  r.x = xv.x + yv.x*ga + be;
  r.y = xv.y + yv.y*ga + be;
  r.z = xv.z + yv.z*ga + be;
  r.w = xv.w + yv.w*ga + be;
  *(float4*)&out[i] = r;
}

// ======================= launch =======================
extern "C" void kernel_launch(void* const* d_in, const int* in_sizes, int n_in,
                              void* d_out, int out_size)
{
  const float* left    = (const float*)d_in[0];
  const float* right   = (const float*)d_in[1];
  const float* pre_l   = (const float*)d_in[2];
  const float* pre_r   = (const float*)d_in[3];
  const float* query_l = (const float*)d_in[4];
  const float* key_l   = (const float*)d_in[5];
  const float* query_r = (const float*)d_in[6];
  const float* key_r   = (const float*)d_in[7];
  const float* theta_w = (const float*)d_in[8];
  const float* theta_b = (const float*)d_in[9];
  const float* phi_w   = (const float*)d_in[10];
  const float* phi_b   = (const float*)d_in[11];
  const float* g_w     = (const float*)d_in[12];
  const float* g_b     = (const float*)d_in[13];
  const float* up_w    = (const float*)d_in[14];
  const float* up_b    = (const float*)d_in[15];
  const float* bn_g    = (const float*)d_in[16];
  const float* bn_b    = (const float*)d_in[17];
  float* out = (float*)d_out;

  cudaFuncSetAttribute(proj_hmma_kernel, cudaFuncAttributeMaxDynamicSharedMemorySize, PJ_SMEM);
  cudaFuncSetAttribute(flash_kernel,     cudaFuncAttributeMaxDynamicSharedMemorySize, FL_SMEM);
  cudaFuncSetAttribute(up_hmma_kernel,   cudaFuncAttributeMaxDynamicSharedMemorySize, UP_SMEM);

  convx_kernel<<<dim3(2048, 2), 256>>>(left, right);
  convw_kernel<<<48, 256>>>(theta_w, phi_w, g_w);

  proj_hmma_kernel<<<dim3(64, NB, 6), 256, PJ_SMEM>>>(
      pre_l, pre_r, query_l, key_l, query_r, key_r,
      theta_w, theta_b, phi_b, g_b);

  flash_kernel<<<dim3(32, KSPLIT, 8), 256, FL_SMEM>>>();

  up_hmma_kernel<<<dim3(32, 8), 256, UP_SMEM>>>(up_w, up_b, out);

  bn_stats_kernel<<<dim3(Cc, 2), 256>>>();

  final_kernel<<<dim3(2*NB*Cc*HW/4/256), 256>>>(left, right, bn_g, bn_b, out);
}

// round 16
// speedup vs baseline: 1.0757x; 1.0681x over previous
#include <cuda_runtime.h>
#include <cstdint>
#include <cstddef>

#define HW   4096
#define Dh   128
#define Cc   256
#define NB   4
#define ST   136   // theta smem row stride (bf16 elems)
#define STB  72    // phi/g/X chunk smem row stride (bf16 elems)
#define BK   64    // key chunk per flash iteration
#define KSPLIT 4
#define NITER (HW/KSPLIT/BK)   // 16

// ======================= helpers =======================
__device__ __forceinline__ uint32_t smem_u32(const void* p) {
  uint32_t a;
  asm("{ .reg .u64 t; cvta.to.shared.u64 t, %1; cvt.u32.u64 %0, t; }" : "=r"(a) : "l"(p));
  return a;
}
__device__ __forceinline__ void ldm_x4(uint32_t a, uint32_t* r) {
  asm volatile("ldmatrix.sync.aligned.m8n8.x4.shared.b16 {%0,%1,%2,%3}, [%4];"
               : "=r"(r[0]), "=r"(r[1]), "=r"(r[2]), "=r"(r[3]) : "r"(a));
}
__device__ __forceinline__ void ldm_x4_t(uint32_t a, uint32_t* r) {
  asm volatile("ldmatrix.sync.aligned.m8n8.x4.trans.shared.b16 {%0,%1,%2,%3}, [%4];"
               : "=r"(r[0]), "=r"(r[1]), "=r"(r[2]), "=r"(r[3]) : "r"(a));
}
__device__ __forceinline__ void hmma(float* d, const uint32_t* a, const uint32_t* b) {
  asm volatile("mma.sync.aligned.m16n8k16.row.col.f32.bf16.bf16.f32 "
               "{%0,%1,%2,%3}, {%4,%5,%6,%7}, {%8,%9}, {%0,%1,%2,%3};"
               : "+f"(d[0]), "+f"(d[1]), "+f"(d[2]), "+f"(d[3])
               : "r"(a[0]), "r"(a[1]), "r"(a[2]), "r"(a[3]), "r"(b[0]), "r"(b[1]));
}
__device__ __forceinline__ void cpasync16(uint32_t dst, const void* src) {
  asm volatile("cp.async.cg.shared.global [%0], [%1], 16;" :: "r"(dst), "l"(src));
}
#define CP_COMMIT() asm volatile("cp.async.commit_group;" ::: "memory")
#define CP_WAIT0()  asm volatile("cp.async.wait_group 0;" ::: "memory")
#define CP_WAIT1()  asm volatile("cp.async.wait_group 1;" ::: "memory")

// bf16 RN-even bits (kept in HIGH half, low 16 zero) — pure int ops, no CVT
__device__ __forceinline__ uint32_t hbits(float x) {
  uint32_t u = __float_as_uint(x);
  return (u + 0x7FFFu + ((u >> 16) & 1u)) & 0xFFFF0000u;
}
// fast exp on FMA/ALU pipes (no MUFU)
__device__ __forceinline__ float fexp(float x) {
  float t = x * 1.4426950408889634f;
  float r = t + 12582912.0f;
  int   n = __float_as_int(r) - 0x4B400000;
  float f = t - (r - 12582912.0f);
  float p = 1.540353e-4f;
  p = fmaf(p, f, 1.3333558e-3f);
  p = fmaf(p, f, 9.6181291e-3f);
  p = fmaf(p, f, 5.5504109e-2f);
  p = fmaf(p, f, 2.4022651e-1f);
  p = fmaf(p, f, 6.9314718e-1f);
  p = fmaf(p, f, 1.0f);
  n = max(n, -126);
  return p * __int_as_float((n + 127) << 23);
}
// RN pack (x,y) -> bf16x2 hi + residual bf16x2 lo (cold paths)
__device__ __forceinline__ void packpair(float x, float y, uint32_t& h, uint32_t& l) {
  uint32_t hx = hbits(x), hy = hbits(y);
  h = __byte_perm(hx, hy, 0x7632);
  float lx = x - __uint_as_float(hx), ly = y - __uint_as_float(hy);
  l = __byte_perm(hbits(lx), hbits(ly), 0x7632);
}
// TRUNC pack (hot PV loop; dropped lo*lo term has random sign)
__device__ __forceinline__ void packpair_t(float x, float y, uint32_t& h, uint32_t& l) {
  uint32_t ux = __float_as_uint(x), uy = __float_as_uint(y);
  h = __byte_perm(ux, uy, 0x7632);
  float lx = x - __uint_as_float(ux & 0xFFFF0000u);
  float ly = y - __uint_as_float(uy & 0xFFFF0000u);
  l = __byte_perm(__float_as_uint(lx), __float_as_uint(ly), 0x7632);
}
// split 8 floats -> bf16 hi/lo packed stores (RN)
__device__ __forceinline__ void split8_store(const float* v, unsigned short* hiP,
                                             unsigned short* loP) {
  uint32_t hw[4], lw[4];
  #pragma unroll
  for (int i = 0; i < 4; i++) {
    uint32_t h0 = hbits(v[2*i]), h1 = hbits(v[2*i+1]);
    hw[i] = __byte_perm(h0, h1, 0x7632);
    float l0 = v[2*i]   - __uint_as_float(h0);
    float l1 = v[2*i+1] - __uint_as_float(h1);
    lw[i] = __byte_perm(hbits(l0), hbits(l1), 0x7632);
  }
  *(uint4*)hiP = make_uint4(hw[0], hw[1], hw[2], hw[3]);
  *(uint4*)loP = make_uint4(lw[0], lw[1], lw[2], lw[3]);
}

// ---------------- scratch (device globals, no allocation) ----------------
#define XN ((size_t)NB*Cc*HW)   // 4194304 elems per source tensor
__device__ unsigned short d_x_hi[2*XN];              // split left/right [src][b][c][hw]
__device__ unsigned short d_x_lo[2*XN];
__device__ unsigned short d_w_hi[3*128*256];         // split weights [proj][d][c]
__device__ unsigned short d_w_lo[3*128*256];
__device__ unsigned short d_th_hi[(size_t)8*Dh*HW];  // theta^T [sb][d][q]
__device__ unsigned short d_th_lo[(size_t)8*Dh*HW];
__device__ unsigned short d_ph_hi[(size_t)8*Dh*HW];  // phi^T   [sb][d][key]
__device__ unsigned short d_ph_lo[(size_t)8*Dh*HW];
__device__ unsigned short d_g_hi [(size_t)8*Dh*HW];  // g^T     [sb][d][k]
__device__ unsigned short d_g_lo [(size_t)8*Dh*HW];
__device__ unsigned short d_af_hi[(size_t)8*HW*Dh];  // after [sb][q][d] (split)
__device__ unsigned short d_af_lo[(size_t)8*HW*Dh];
__device__ float  d_op [(size_t)KSPLIT*8*HW*Dh];     // unnormalized O partials
__device__ float2 d_lcp[(size_t)KSPLIT*8*HW];        // (l, c) partials
__device__ float  d_y    [(size_t)8*Cc*HW];
__device__ float2 d_bn   [2*Cc];

// ======================= input conversion (X and W merged, one launch) =========
// grid 4144: blocks 0..4095 convert X (2048 per source), 4096..4143 convert W
__global__ __launch_bounds__(256) void conv_kernel(
    const float* __restrict__ left, const float* __restrict__ right,
    const float* __restrict__ theta_w, const float* __restrict__ phi_w,
    const float* __restrict__ g_w)
{
  int blk = blockIdx.x;
  if (blk < 4096) {
    int srcid = blk >> 11;
    const float* src = srcid ? right : left;
    size_t off = ((size_t)(blk & 2047)*256 + threadIdx.x) * 8;
    float v[8];
    *(float4*)&v[0] = *(const float4*)&src[off];
    *(float4*)&v[4] = *(const float4*)&src[off + 4];
    size_t o = (size_t)srcid*XN + off;
    split8_store(v, &d_x_hi[o], &d_x_lo[o]);
  } else {
    int i = ((blk - 4096)*256 + threadIdx.x) * 8;
    int proj = i >> 15;
    int rem  = i & 32767;
    int d = rem >> 8, c8 = rem & 255;
    const float* w = proj == 0 ? theta_w : (proj == 1 ? phi_w : g_w);
    int cin = proj == 0 ? 257 : 256;
    float v[8];
    #pragma unroll
    for (int j = 0; j < 8; j++) v[j] = w[(size_t)d*cin + c8 + j];
    split8_store(v, &d_w_hi[i], &d_w_lo[i]);
  }
}

// ======================= projection (theta/phi/g) — HMMA v2 ====================
#define PJ_SMEM 208896
__global__ __launch_bounds__(256, 1) void proj_hmma_kernel(
    const float* __restrict__ pre_l,  const float* __restrict__ pre_r,
    const float* __restrict__ query_l,const float* __restrict__ key_l,
    const float* __restrict__ query_r,const float* __restrict__ key_r,
    const float* __restrict__ theta_w,const float* __restrict__ theta_b,
    const float* __restrict__ phi_b,  const float* __restrict__ g_b)
{
  extern __shared__ char smem[];
  const uint32_t sb32 = smem_u32(smem);
  const int qt = blockIdx.x, b = blockIdx.y, z = blockIdx.z;
  const int side = z / 3, proj = z - side*3;
  const int tid = threadIdx.x, wid = tid >> 5, lid = tid & 31;
  const int q0 = qt * 64;

  const int srcidx = (proj == 0) ? side : (1 - side);
  const unsigned short* xh = d_x_hi + (size_t)srcidx*XN + (size_t)b*Cc*HW;
  const unsigned short* xl = d_x_lo + (size_t)srcidx*XN + (size_t)b*Cc*HW;
  const unsigned short* wh = d_w_hi + proj*128*256;
  const unsigned short* wl = d_w_lo + proj*128*256;

  #pragma unroll
  for (int t = 0; t < 16; t++) {
    int i = tid + t*256;
    int d = i >> 5, p = (i & 31) * 8;
    uint32_t o = (uint32_t)(d*264 + p) * 2;
    cpasync16(sb32 + 0u     + o, wh + (size_t)d*256 + p);
    cpasync16(sb32 + 67584u + o, wl + (size_t)d*256 + p);
  }
  auto issue_x = [&](int buf, int c0) {
    uint32_t XB = sb32 + 135168u + (uint32_t)buf*36864u;
    #pragma unroll
    for (int t = 0; t < 4; t++) {
      int i = tid + t*256;
      int r = i >> 3, p = (i & 7) * 8;
      uint32_t o = (uint32_t)(r*STB + p) * 2;
      size_t go = (size_t)(c0 + r)*HW + q0 + p;
      cpasync16(XB + o,          xh + go);
      cpasync16(XB + 18432u + o, xl + go);
    }
  };
  issue_x(0, 0);
  CP_COMMIT();
  issue_x(1, 128);
  CP_COMMIT();

  const int dm0  = wid * 16;
  const int arow = lid & 15;
  const int akh  = (lid & 16) ? 8 : 0;
  const int trow = lid & 15;
  const int tnh  = (lid & 16) ? 8 : 0;

  float acc[8][4];
  #pragma unroll
  for (int nf = 0; nf < 8; nf++)
    #pragma unroll
    for (int e = 0; e < 4; e++) acc[nf][e] = 0.f;

  #pragma unroll 1
  for (int ch = 0; ch < 2; ch++) {
    if (ch == 0) { CP_WAIT1(); } else { CP_WAIT0(); }
    __syncthreads();
    const int cofs = ch * 128;
    const uint32_t XH = sb32 + 135168u + (uint32_t)ch*36864u;
    const uint32_t XL = XH + 18432u;
    #pragma unroll
    for (int k16 = 0; k16 < 8; k16++) {
      uint32_t ah[4], al[4];
      ldm_x4(sb32 + 0u     + ((dm0 + arow)*264 + cofs + k16*16 + akh)*2, ah);
      ldm_x4(sb32 + 67584u + ((dm0 + arow)*264 + cofs + k16*16 + akh)*2, al);
      #pragma unroll
      for (int nq = 0; nq < 4; nq++) {
        uint32_t bh[4], bl[4];
        ldm_x4_t(XH + ((k16*16 + trow)*STB + nq*16 + tnh)*2, bh);
        hmma(acc[2*nq],   ah, bh);
        hmma(acc[2*nq+1], ah, bh + 2);
        hmma(acc[2*nq],   al, bh);
        hmma(acc[2*nq+1], al, bh + 2);
        ldm_x4_t(XL + ((k16*16 + trow)*STB + nq*16 + tnh)*2, bl);
        hmma(acc[2*nq],   ah, bl);
        hmma(acc[2*nq+1], ah, bl + 2);
      }
    }
  }

  const int sb = side*NB + b;
  const int d0 = dm0 + (lid >> 2), d1 = d0 + 8;
  unsigned short* dstH;
  unsigned short* dstL;
  const float* bias;
  if (proj == 0)      { dstH = d_th_hi; dstL = d_th_lo; bias = theta_b; }
  else if (proj == 1) { dstH = d_ph_hi; dstL = d_ph_lo; bias = phi_b; }
  else                { dstH = d_g_hi;  dstL = d_g_lo;  bias = g_b; }
  size_t r0 = ((size_t)sb*Dh + d0)*HW;
  size_t r1 = ((size_t)sb*Dh + d1)*HW;
  const float b0 = bias[d0], b1 = bias[d1];

  if (proj == 0) {
    const float* pre = side ? pre_r : pre_l;
    const float* qry = side ? query_r : query_l;
    const float wl0 = theta_w[(size_t)d0*257 + 256];
    const float wl1 = theta_w[(size_t)d1*257 + 256];
    const float* q0p = qry + ((size_t)b*Dh + d0)*HW;
    const float* q1p = qry + ((size_t)b*Dh + d1)*HW;
    #pragma unroll
    for (int nf = 0; nf < 8; nf++) {
      int q = q0 + nf*8 + (lid & 3)*2;
      float2 pr = *(const float2*)&pre[(size_t)b*HW + q];
      pr.x *= (1.0f/128.0f); pr.y *= (1.0f/128.0f);
      float2 qv0 = *(const float2*)&q0p[q];
      float2 qv1 = *(const float2*)&q1p[q];
      uint32_t h, l;
      packpair(acc[nf][0] + b0 + wl0*pr.x + qv0.x,
               acc[nf][1] + b0 + wl0*pr.y + qv0.y, h, l);
      *(uint32_t*)&dstH[r0 + q] = h;
      *(uint32_t*)&dstL[r0 + q] = l;
      packpair(acc[nf][2] + b1 + wl1*pr.x + qv1.x,
               acc[nf][3] + b1 + wl1*pr.y + qv1.y, h, l);
      *(uint32_t*)&dstH[r1 + q] = h;
      *(uint32_t*)&dstL[r1 + q] = l;
    }
  } else if (proj == 1) {
    const float* kf = side ? key_l : key_r;
    const float* k0p = kf + ((size_t)b*Dh + d0)*HW;
    const float* k1p = kf + ((size_t)b*Dh + d1)*HW;
    #pragma unroll
    for (int nf = 0; nf < 8; nf++) {
      int q = q0 + nf*8 + (lid & 3)*2;
      float2 kv0 = *(const float2*)&k0p[q];
      float2 kv1 = *(const float2*)&k1p[q];
      uint32_t h, l;
      packpair(acc[nf][0] + b0 + kv0.x, acc[nf][1] + b0 + kv0.y, h, l);
      *(uint32_t*)&dstH[r0 + q] = h;
      *(uint32_t*)&dstL[r0 + q] = l;
      packpair(acc[nf][2] + b1 + kv1.x, acc[nf][3] + b1 + kv1.y, h, l);
      *(uint32_t*)&dstH[r1 + q] = h;
      *(uint32_t*)&dstL[r1 + q] = l;
    }
  } else {
    #pragma unroll
    for (int nf = 0; nf < 8; nf++) {
      int q = q0 + nf*8 + (lid & 3)*2;
      uint32_t h, l;
      packpair(acc[nf][0] + b0, acc[nf][1] + b0, h, l);
      *(uint32_t*)&dstH[r0 + q] = h;
      *(uint32_t*)&dstL[r0 + q] = l;
      packpair(acc[nf][2] + b1, acc[nf][3] + b1, h, l);
      *(uint32_t*)&dstH[r1 + q] = h;
      *(uint32_t*)&dstL[r1 + q] = l;
    }
  }
}

// ======================= fused flash attention (HMMA, split-bf16) ===============
// R13 structure + theta-hi fragments hoisted into registers (iteration-invariant)
#define TH_HI_OFF 0u
#define TH_LO_OFF 34816u
#define BUF_OFF   69632u     // + buf*73728: phi hi, +18432 lo, +36864 g hi, +55296 g lo
#define FL_SMEM   217088

__global__ __launch_bounds__(256, 1) void flash_kernel()
{
  extern __shared__ char smem[];
  const uint32_t sb32 = smem_u32(smem);
  const int mtile = blockIdx.x, split = blockIdx.y, sb = blockIdx.z;
  const int tid = threadIdx.x, wid = tid >> 5, lid = tid & 31;
  const int q0 = mtile * 128;
  const int kbase0 = split * (HW / KSPLIT);

  const unsigned short* thH = d_th_hi + (size_t)sb*Dh*HW + q0;
  const unsigned short* thL = d_th_lo + (size_t)sb*Dh*HW + q0;
  const unsigned short* phH = d_ph_hi + (size_t)sb*Dh*HW;
  const unsigned short* phL = d_ph_lo + (size_t)sb*Dh*HW;
  const unsigned short* gH  = d_g_hi  + (size_t)sb*Dh*HW;
  const unsigned short* gL  = d_g_lo  + (size_t)sb*Dh*HW;

  #pragma unroll
  for (int t = 0; t < 8; t++) {
    int i = tid + t*256;
    int r = i >> 4, c8 = (i & 15) * 8;
    uint32_t o = (uint32_t)(r*ST + c8) * 2;
    size_t go = (size_t)r*HW + c8;
    *(uint4*)(smem + TH_HI_OFF + o) = *(const uint4*)&thH[go];
    *(uint4*)(smem + TH_LO_OFF + o) = *(const uint4*)&thL[go];
  }

  auto issue_chunk = [&](int buf, int kb) {
    uint32_t PB = sb32 + BUF_OFF + (uint32_t)buf*73728u;
    uint32_t GB = PB + 36864u;
    #pragma unroll
    for (int t = 0; t < 4; t++) {
      int i = tid + t*256;
      int r = i >> 3, p = (i & 7) * 8;
      uint32_t o = (uint32_t)(r*STB + p) * 2;
      size_t go = (size_t)r*HW + kb + p;
      cpasync16(PB + o,          phH + go);
      cpasync16(PB + 18432u + o, phL + go);
      cpasync16(GB + o,          gH + go);
      cpasync16(GB + 18432u + o, gL + go);
    }
  };

  issue_chunk(0, kbase0);
  CP_COMMIT();

  const int m0   = wid * 16;
  const int trow = lid & 15;
  const int tnh  = (lid & 16) ? 8 : 0;
  const int brow = (lid & 7) + ((lid & 16) ? 8 : 0);
  const int bkh  = (lid & 8) ? 8 : 0;
  const float wbase = (float)((lid & 3) * 2);

  // theta smem now complete for this CTA; hoist iteration-invariant hi A-frags
  __syncthreads();
  uint32_t thA[8][4];
  #pragma unroll
  for (int k16 = 0; k16 < 8; k16++) {
    uint32_t rh[4];
    ldm_x4_t(sb32 + TH_HI_OFF + ((k16*16 + trow)*ST + m0 + tnh)*2, rh);
    thA[k16][0] = rh[0]; thA[k16][1] = rh[2];
    thA[k16][2] = rh[1]; thA[k16][3] = rh[3];
  }

  float O[16][4];
  #pragma unroll
  for (int nf = 0; nf < 16; nf++)
    #pragma unroll
    for (int e = 0; e < 4; e++) O[nf][e] = 0.f;
  float lacc0 = 0.f, lacc1 = 0.f, cacc0 = 0.f, cacc1 = 0.f;

  #pragma unroll 1
  for (int it = 0; it < NITER; it++) {
    const int buf = it & 1;
    CP_WAIT0();
    __syncthreads();   // chunk `it` visible; all warps finished it-1's reads

    const uint32_t PH = sb32 + BUF_OFF + (uint32_t)buf*73728u;
    const uint32_t PL = PH + 18432u;
    const uint32_t GHs = PH + 36864u;
    const uint32_t GLs = GHs + 18432u;

    // ---- S = theta phi^T (theta hi from registers, lo from smem) ----
    float acc[8][4];
    #pragma unroll
    for (int nf = 0; nf < 8; nf++)
      #pragma unroll
      for (int e = 0; e < 4; e++) acc[nf][e] = 0.f;

    #pragma unroll
    for (int k16 = 0; k16 < 8; k16++) {
      uint32_t rl[4];
      ldm_x4_t(sb32 + TH_LO_OFF + ((k16*16 + trow)*ST + m0 + tnh)*2, rl);
      uint32_t al[4] = {rl[0], rl[2], rl[1], rl[3]};
      const uint32_t* ah = thA[k16];
      #pragma unroll
      for (int nb = 0; nb < 4; nb++) {
        uint32_t bh[4], bl[4];
        ldm_x4_t(PH + ((k16*16 + trow)*STB + nb*16 + tnh)*2, bh);
        hmma(acc[2*nb],   ah, bh);
        hmma(acc[2*nb+1], ah, bh + 2);
        hmma(acc[2*nb],   al, bh);
        hmma(acc[2*nb+1], al, bh + 2);
        ldm_x4_t(PL + ((k16*16 + trow)*STB + nb*16 + tnh)*2, bl);
        hmma(acc[2*nb],   ah, bl);
        hmma(acc[2*nb+1], ah, bl + 2);
      }
    }

    // ---- exp + l/c row sums ----
    const float wof = wbase + (buf ? 64.0f : 0.0f);
    #pragma unroll
    for (int nf = 0; nf < 8; nf++) {
      float w0 = wof + (float)(nf*8), w1 = w0 + 1.0f;
      float p0 = fexp(acc[nf][0]), p1 = fexp(acc[nf][1]);
      float p2 = fexp(acc[nf][2]), p3 = fexp(acc[nf][3]);
      acc[nf][0] = p0; acc[nf][1] = p1; acc[nf][2] = p2; acc[nf][3] = p3;
      lacc0 += p0 + p1;               lacc1 += p2 + p3;
      cacc0 += p0*w0 + p1*w1;         cacc1 += p2*w0 + p3*w1;
    }

    // ---- prefetch next chunk (mid-iteration placement — R13-verified) ----
    if (it + 1 < NITER) {
      issue_chunk(buf ^ 1, kbase0 + (it + 1)*BK);
      CP_COMMIT();
    }

    // ---- O += P g (trunc split of P) ----
    #pragma unroll
    for (int kk = 0; kk < 4; kk++) {
      uint32_t a_h[4], a_l[4];
      packpair_t(acc[2*kk][0],   acc[2*kk][1],   a_h[0], a_l[0]);
      packpair_t(acc[2*kk][2],   acc[2*kk][3],   a_h[1], a_l[1]);
      packpair_t(acc[2*kk+1][0], acc[2*kk+1][1], a_h[2], a_l[2]);
      packpair_t(acc[2*kk+1][2], acc[2*kk+1][3], a_h[3], a_l[3]);
      #pragma unroll
      for (int nb = 0; nb < 8; nb++) {
        uint32_t bh[4], bl[4];
        ldm_x4(GHs + ((nb*16 + brow)*STB + kk*16 + bkh)*2, bh);
        hmma(O[2*nb],   a_h, bh);
        hmma(O[2*nb+1], a_h, bh + 2);
        hmma(O[2*nb],   a_l, bh);
        hmma(O[2*nb+1], a_l, bh + 2);
        ldm_x4(GLs + ((nb*16 + brow)*STB + kk*16 + bkh)*2, bl);
        hmma(O[2*nb],   a_h, bl);
        hmma(O[2*nb+1], a_h, bl + 2);
      }
    }
  }

  #pragma unroll
  for (int off = 1; off <= 2; off <<= 1) {
    lacc0 += __shfl_xor_sync(0xffffffffu, lacc0, off);
    lacc1 += __shfl_xor_sync(0xffffffffu, lacc1, off);
    cacc0 += __shfl_xor_sync(0xffffffffu, cacc0, off);
    cacc1 += __shfl_xor_sync(0xffffffffu, cacc1, off);
  }

  const int r0 = q0 + m0 + (lid >> 2);
  const int ssb = split*8 + sb;
  {
    float* o0 = d_op + ((size_t)ssb*HW + r0)*Dh + (lid & 3)*2;
    float* o1 = o0 + (size_t)8*Dh;
    #pragma unroll
    for (int nf = 0; nf < 16; nf++) {
      *(float2*)&o0[nf*8] = make_float2(O[nf][0], O[nf][1]);
      *(float2*)&o1[nf*8] = make_float2(O[nf][2], O[nf][3]);
    }
  }
  if ((lid & 3) == 0) {
    d_lcp[(size_t)ssb*HW + r0]     = make_float2(lacc0, cacc0);
    d_lcp[(size_t)ssb*HW + r0 + 8] = make_float2(lacc1, cacc1);
  }
}

// ======================= combine partials: normalize -> split bf16, index =======
__global__ __launch_bounds__(128) void combine_kernel(float* __restrict__ out)
{
  const int t = threadIdx.x, sb = blockIdx.y;
  const int q = blockIdx.x*2 + (t >> 6);
  const int d2 = (t & 63) * 2;
  float l = 0.f, c = 0.f;
  #pragma unroll
  for (int s = 0; s < KSPLIT; s++) {
    float2 lc = d_lcp[(size_t)(s*8 + sb)*HW + q];
    l += lc.x; c += lc.y;
  }
  float o0 = 0.f, o1 = 0.f;
  #pragma unroll
  for (int s = 0; s < KSPLIT; s++) {
    float2 v = *(const float2*)&d_op[((size_t)(s*8 + sb)*HW + q)*Dh + d2];
    o0 += v.x; o1 += v.y;
  }
  float inv = 1.0f / l;
  uint32_t h, lo;
  packpair(o0*inv, o1*inv, h, lo);
  *(uint32_t*)&d_af_hi[((size_t)sb*HW + q)*Dh + d2] = h;
  *(uint32_t*)&d_af_lo[((size_t)sb*HW + q)*Dh + d2] = lo;
  if ((t & 63) == 0)
    out[(size_t)2*NB*Cc*HW + (size_t)sb*HW + q] = (float)(q & 127) - c * inv;
}

// ======================= up-projection — HMMA (R13-verified) ====================
#define UP_SMEM 208896
__global__ __launch_bounds__(256, 1) void up_hmma_kernel(
    const float* __restrict__ up_w, const float* __restrict__ up_b)
{
  extern __shared__ char smem[];
  const uint32_t sb32 = smem_u32(smem);
  const int qtile = blockIdx.x, sb = blockIdx.y;
  const int tid = threadIdx.x, wid = tid >> 5, lid = tid & 31;
  const int q0 = qtile * 128;

  #pragma unroll
  for (int t = 0; t < 64; t++) {
    int i = tid + t*256;
    int cc = i >> 6, dd2 = (i & 63) * 2;
    float2 v = *(const float2*)&up_w[(size_t)cc*Dh + dd2];
    uint32_t h, l; packpair(v.x, v.y, h, l);
    uint32_t o = (uint32_t)(cc*ST + dd2) * 2;
    *(uint32_t*)(smem + 0u     + o) = h;
    *(uint32_t*)(smem + 69632u + o) = l;
  }
  {
    const unsigned short* bH = d_af_hi + ((size_t)sb*HW + q0)*Dh;
    const unsigned short* bL = d_af_lo + ((size_t)sb*HW + q0)*Dh;
    #pragma unroll
    for (int t = 0; t < 8; t++) {
      int i = tid + t*256;
      int r = i >> 4, c8 = (i & 15) * 8;
      uint32_t o = (uint32_t)(r*ST + c8) * 2;
      size_t go = (size_t)r*Dh + c8;
      *(uint4*)(smem + 139264u + o) = *(const uint4*)&bH[go];
      *(uint4*)(smem + 174080u + o) = *(const uint4*)&bL[go];
    }
  }
  __syncthreads();

  const int m0   = wid * 32;
  const int arow = lid & 15;
  const int akh  = (lid & 16) ? 8 : 0;
  const int brow = (lid & 7) + ((lid & 16) ? 8 : 0);
  const int bkh  = (lid & 8) ? 8 : 0;

  float acc[2][16][4];
  #pragma unroll
  for (int mf = 0; mf < 2; mf++)
    #pragma unroll
    for (int nf = 0; nf < 16; nf++)
      #pragma unroll
      for (int e = 0; e < 4; e++) acc[mf][nf][e] = 0.f;

  #pragma unroll
  for (int k16 = 0; k16 < 8; k16++) {
    uint32_t ah[2][4], al[2][4];
    #pragma unroll
    for (int mf = 0; mf < 2; mf++) {
      ldm_x4(sb32 + 0u     + ((m0 + mf*16 + arow)*ST + k16*16 + akh)*2, ah[mf]);
      ldm_x4(sb32 + 69632u + ((m0 + mf*16 + arow)*ST + k16*16 + akh)*2, al[mf]);
    }
    #pragma unroll
    for (int nb = 0; nb < 8; nb++) {
      uint32_t bh[4], bl[4];
      ldm_x4(sb32 + 139264u + ((nb*16 + brow)*ST + k16*16 + bkh)*2, bh);
      ldm_x4(sb32 + 174080u + ((nb*16 + brow)*ST + k16*16 + bkh)*2, bl);
      #pragma unroll
      for (int mf = 0; mf < 2; mf++) {
        hmma(acc[mf][2*nb],   ah[mf], bh);
        hmma(acc[mf][2*nb+1], ah[mf], bh + 2);
        hmma(acc[mf][2*nb],   al[mf], bh);
        hmma(acc[mf][2*nb+1], al[mf], bh + 2);
        hmma(acc[mf][2*nb],   ah[mf], bl);
        hmma(acc[mf][2*nb+1], ah[mf], bl + 2);
      }
    }
  }

  float* Yp = d_y + (size_t)sb*Cc*HW;
  #pragma unroll
  for (int mf = 0; mf < 2; mf++) {
    const int c0 = m0 + mf*16 + (lid >> 2);
    float bb0 = up_b[c0], bb1 = up_b[c0 + 8];
    #pragma unroll
    for (int nf = 0; nf < 16; nf++) {
      int qq = q0 + nf*8 + (lid & 3)*2;
      *(float2*)&Yp[(size_t)c0*HW + qq] =
          make_float2(acc[mf][nf][0] + bb0, acc[mf][nf][1] + bb0);
      *(float2*)&Yp[(size_t)(c0+8)*HW + qq] =
          make_float2(acc[mf][nf][2] + bb1, acc[mf][nf][3] + bb1);
    }
  }
}

// ======================= BN stats =======================
__global__ __launch_bounds__(256) void bn_stats_kernel()
{
  const int c = blockIdx.x, side = blockIdx.y;
  float s = 0.f, s2 = 0.f;
  for (int b = 0; b < NB; b++) {
    const float* p = d_y + (size_t)((side*NB + b)*Cc + c)*HW;
    for (int i = threadIdx.x; i < HW; i += 256) {
      float v = p[i];
      s += v; s2 += v*v;
    }
  }
  __shared__ float red[64];
  #pragma unroll
  for (int off = 16; off; off >>= 1) {
    s  += __shfl_down_sync(0xffffffffu, s,  off);
    s2 += __shfl_down_sync(0xffffffffu, s2, off);
  }
  int w = threadIdx.x >> 5;
  if ((threadIdx.x & 31) == 0) { red[w] = s; red[w + 32] = s2; }
  __syncthreads();
  if (threadIdx.x == 0) {
    float ts = 0.f, ts2 = 0.f;
    #pragma unroll
    for (int i = 0; i < 8; i++) { ts += red[i]; ts2 += red[i + 32]; }
    float mean = ts * (1.0f/16384.0f);
    float var  = ts2 * (1.0f/16384.0f) - mean*mean;
    d_bn[side*Cc + c] = make_float2(mean, rsqrtf(var + 1e-5f));
  }
}

// ======================= final: residual + BN apply =======================
__global__ __launch_bounds__(256) void final_kernel(
    const float* __restrict__ left, const float* __restrict__ right,
    const float* __restrict__ gamma, const float* __restrict__ beta,
    float* __restrict__ out)
{
  size_t i = ((size_t)blockIdx.x*256 + threadIdx.x) * 4;
  int q = (int)(i & 4095);
  size_t t = i >> 12;
  int c = (int)(t & 255); t >>= 8;
  int b = (int)(t & 3);
  int side = (int)(t >> 2);
  const float* x = side ? right : left;
  float4 xv = *(const float4*)&x[(((size_t)b*Cc + c) << 12) + q];
  float4 yv = *(const float4*)&d_y[i];
  float2 st = d_bn[side*Cc + c];
  float ga = gamma[c]*st.y;
  float be = beta[c] - ga*st.x;
  float4 r;
  r.x = xv.x + yv.x*ga + be;
  r.y = xv.y + yv.y*ga + be;
  r.z = xv.z + yv.z*ga + be;
  r.w = xv.w + yv.w*ga + be;
  *(float4*)&out[i] = r;
}

// ======================= launch =======================
extern "C" void kernel_launch(void* const* d_in, const int* in_sizes, int n_in,
                              void* d_out, int out_size)
{
  const float* left    = (const float*)d_in[0];
  const float* right   = (const float*)d_in[1];
  const float* pre_l   = (const float*)d_in[2];
  const float* pre_r   = (const float*)d_in[3];
  const float* query_l = (const float*)d_in[4];
  const float* key_l   = (const float*)d_in[5];
  const float* query_r = (const float*)d_in[6];
  const float* key_r   = (const float*)d_in[7];
  const float* theta_w = (const float*)d_in[8];
  const float* theta_b = (const float*)d_in[9];
  const float* phi_w   = (const float*)d_in[10];
  const float* phi_b   = (const float*)d_in[11];
  const float* g_w     = (const float*)d_in[12];
  const float* g_b     = (const float*)d_in[13];
  const float* up_w    = (const float*)d_in[14];
  const float* up_b    = (const float*)d_in[15];
  const float* bn_g    = (const float*)d_in[16];
  const float* bn_b    = (const float*)d_in[17];
  float* out = (float*)d_out;

  cudaFuncSetAttribute(proj_hmma_kernel, cudaFuncAttributeMaxDynamicSharedMemorySize, PJ_SMEM);
  cudaFuncSetAttribute(flash_kernel,     cudaFuncAttributeMaxDynamicSharedMemorySize, FL_SMEM);
  cudaFuncSetAttribute(up_hmma_kernel,   cudaFuncAttributeMaxDynamicSharedMemorySize, UP_SMEM);

  conv_kernel<<<4144, 256>>>(left, right, theta_w, phi_w, g_w);

  proj_hmma_kernel<<<dim3(64, NB, 6), 256, PJ_SMEM>>>(
      pre_l, pre_r, query_l, key_l, query_r, key_r,
      theta_w, theta_b, phi_b, g_b);

  flash_kernel<<<dim3(32, KSPLIT, 8), 256, FL_SMEM>>>();

  combine_kernel<<<dim3(HW/2, 8), 128>>>(out);

  up_hmma_kernel<<<dim3(32, 8), 256, UP_SMEM>>>(up_w, up_b);

  bn_stats_kernel<<<dim3(Cc, 2), 256>>>();

  final_kernel<<<dim3(2*NB*Cc*HW/4/256), 256>>>(left, right, bn_g, bn_b, out);
}

// round 17
// speedup vs baseline: 1.0779x; 1.0020x over previous
#include <cuda_runtime.h>
#include <cstdint>
#include <cstddef>

#define HW   4096
#define Dh   128
#define Cc   256
#define NB   4
#define ST   136   // theta smem row stride (bf16 elems)
#define STB  72    // phi/g/X chunk smem row stride (bf16 elems)
#define BK   64    // key chunk per flash iteration
#define KSPLIT 4
#define NITER (HW/KSPLIT/BK)   // 16

// ======================= helpers =======================
__device__ __forceinline__ uint32_t smem_u32(const void* p) {
  uint32_t a;
  asm("{ .reg .u64 t; cvta.to.shared.u64 t, %1; cvt.u32.u64 %0, t; }" : "=r"(a) : "l"(p));
  return a;
}
__device__ __forceinline__ void ldm_x4(uint32_t a, uint32_t* r) {
  asm volatile("ldmatrix.sync.aligned.m8n8.x4.shared.b16 {%0,%1,%2,%3}, [%4];"
               : "=r"(r[0]), "=r"(r[1]), "=r"(r[2]), "=r"(r[3]) : "r"(a));
}
__device__ __forceinline__ void ldm_x4_t(uint32_t a, uint32_t* r) {
  asm volatile("ldmatrix.sync.aligned.m8n8.x4.trans.shared.b16 {%0,%1,%2,%3}, [%4];"
               : "=r"(r[0]), "=r"(r[1]), "=r"(r[2]), "=r"(r[3]) : "r"(a));
}
__device__ __forceinline__ void hmma(float* d, const uint32_t* a, const uint32_t* b) {
  asm volatile("mma.sync.aligned.m16n8k16.row.col.f32.bf16.bf16.f32 "
               "{%0,%1,%2,%3}, {%4,%5,%6,%7}, {%8,%9}, {%0,%1,%2,%3};"
               : "+f"(d[0]), "+f"(d[1]), "+f"(d[2]), "+f"(d[3])
               : "r"(a[0]), "r"(a[1]), "r"(a[2]), "r"(a[3]), "r"(b[0]), "r"(b[1]));
}
__device__ __forceinline__ void cpasync16(uint32_t dst, const void* src) {
  asm volatile("cp.async.cg.shared.global [%0], [%1], 16;" :: "r"(dst), "l"(src));
}
#define CP_COMMIT() asm volatile("cp.async.commit_group;" ::: "memory")
#define CP_WAIT0()  asm volatile("cp.async.wait_group 0;" ::: "memory")
#define CP_WAIT1()  asm volatile("cp.async.wait_group 1;" ::: "memory")

// bf16 RN-even bits (kept in HIGH half, low 16 zero) — pure int ops, no CVT
__device__ __forceinline__ uint32_t hbits(float x) {
  uint32_t u = __float_as_uint(x);
  return (u + 0x7FFFu + ((u >> 16) & 1u)) & 0xFFFF0000u;
}
// fast exp on FMA/ALU pipes (no MUFU)
__device__ __forceinline__ float fexp(float x) {
  float t = x * 1.4426950408889634f;
  float r = t + 12582912.0f;
  int   n = __float_as_int(r) - 0x4B400000;
  float f = t - (r - 12582912.0f);
  float p = 1.540353e-4f;
  p = fmaf(p, f, 1.3333558e-3f);
  p = fmaf(p, f, 9.6181291e-3f);
  p = fmaf(p, f, 5.5504109e-2f);
  p = fmaf(p, f, 2.4022651e-1f);
  p = fmaf(p, f, 6.9314718e-1f);
  p = fmaf(p, f, 1.0f);
  n = max(n, -126);
  return p * __int_as_float((n + 127) << 23);
}
// RN pack (x,y) -> bf16x2 hi + residual bf16x2 lo (cold paths)
__device__ __forceinline__ void packpair(float x, float y, uint32_t& h, uint32_t& l) {
  uint32_t hx = hbits(x), hy = hbits(y);
  h = __byte_perm(hx, hy, 0x7632);
  float lx = x - __uint_as_float(hx), ly = y - __uint_as_float(hy);
  l = __byte_perm(hbits(lx), hbits(ly), 0x7632);
}
// TRUNC pack (hot PV loop; dropped lo*lo term has random sign)
__device__ __forceinline__ void packpair_t(float x, float y, uint32_t& h, uint32_t& l) {
  uint32_t ux = __float_as_uint(x), uy = __float_as_uint(y);
  h = __byte_perm(ux, uy, 0x7632);
  float lx = x - __uint_as_float(ux & 0xFFFF0000u);
  float ly = y - __uint_as_float(uy & 0xFFFF0000u);
  l = __byte_perm(__float_as_uint(lx), __float_as_uint(ly), 0x7632);
}
// split 8 floats -> bf16 hi/lo packed stores (RN)
__device__ __forceinline__ void split8_store(const float* v, unsigned short* hiP,
                                             unsigned short* loP) {
  uint32_t hw[4], lw[4];
  #pragma unroll
  for (int i = 0; i < 4; i++) {
    uint32_t h0 = hbits(v[2*i]), h1 = hbits(v[2*i+1]);
    hw[i] = __byte_perm(h0, h1, 0x7632);
    float l0 = v[2*i]   - __uint_as_float(h0);
    float l1 = v[2*i+1] - __uint_as_float(h1);
    lw[i] = __byte_perm(hbits(l0), hbits(l1), 0x7632);
  }
  *(uint4*)hiP = make_uint4(hw[0], hw[1], hw[2], hw[3]);
  *(uint4*)loP = make_uint4(lw[0], lw[1], lw[2], lw[3]);
}

// ---------------- scratch (device globals, no allocation) ----------------
#define XN ((size_t)NB*Cc*HW)   // 4194304 elems per source tensor
__device__ unsigned short d_x_hi[2*XN];              // split left/right [src][b][c][hw]
__device__ unsigned short d_x_lo[2*XN];
__device__ unsigned short d_w_hi[3*128*256];         // split weights [proj][d][c]
__device__ unsigned short d_w_lo[3*128*256];
__device__ unsigned short d_th_hi[(size_t)8*Dh*HW];  // theta^T [sb][d][q]
__device__ unsigned short d_th_lo[(size_t)8*Dh*HW];
__device__ unsigned short d_ph_hi[(size_t)8*Dh*HW];  // phi^T   [sb][d][key]
__device__ unsigned short d_ph_lo[(size_t)8*Dh*HW];
__device__ unsigned short d_g_hi [(size_t)8*Dh*HW];  // g^T     [sb][d][k]
__device__ unsigned short d_g_lo [(size_t)8*Dh*HW];
__device__ unsigned short d_af_hi[(size_t)8*HW*Dh];  // after [sb][q][d] (split)
__device__ unsigned short d_af_lo[(size_t)8*HW*Dh];
__device__ float  d_op [(size_t)KSPLIT*8*HW*Dh];     // unnormalized O partials
__device__ float2 d_lcp[(size_t)KSPLIT*8*HW];        // (l, c) partials
__device__ float  d_y    [(size_t)8*Cc*HW];
__device__ float2 d_bn   [2*Cc];

// ======================= input conversion (X and W merged, one launch) =========
__global__ __launch_bounds__(256) void conv_kernel(
    const float* __restrict__ left, const float* __restrict__ right,
    const float* __restrict__ theta_w, const float* __restrict__ phi_w,
    const float* __restrict__ g_w)
{
  int blk = blockIdx.x;
  if (blk < 4096) {
    int srcid = blk >> 11;
    const float* src = srcid ? right : left;
    size_t off = ((size_t)(blk & 2047)*256 + threadIdx.x) * 8;
    float v[8];
    *(float4*)&v[0] = *(const float4*)&src[off];
    *(float4*)&v[4] = *(const float4*)&src[off + 4];
    size_t o = (size_t)srcid*XN + off;
    split8_store(v, &d_x_hi[o], &d_x_lo[o]);
  } else {
    int i = ((blk - 4096)*256 + threadIdx.x) * 8;
    int proj = i >> 15;
    int rem  = i & 32767;
    int d = rem >> 8, c8 = rem & 255;
    const float* w = proj == 0 ? theta_w : (proj == 1 ? phi_w : g_w);
    int cin = proj == 0 ? 257 : 256;
    float v[8];
    #pragma unroll
    for (int j = 0; j < 8; j++) v[j] = w[(size_t)d*cin + c8 + j];
    split8_store(v, &d_w_hi[i], &d_w_lo[i]);
  }
}

// ======================= projection (theta/phi/g) — HMMA v2 ====================
#define PJ_SMEM 208896
__global__ __launch_bounds__(256, 1) void proj_hmma_kernel(
    const float* __restrict__ pre_l,  const float* __restrict__ pre_r,
    const float* __restrict__ query_l,const float* __restrict__ key_l,
    const float* __restrict__ query_r,const float* __restrict__ key_r,
    const float* __restrict__ theta_w,const float* __restrict__ theta_b,
    const float* __restrict__ phi_b,  const float* __restrict__ g_b)
{
  extern __shared__ char smem[];
  const uint32_t sb32 = smem_u32(smem);
  const int qt = blockIdx.x, b = blockIdx.y, z = blockIdx.z;
  const int side = z / 3, proj = z - side*3;
  const int tid = threadIdx.x, wid = tid >> 5, lid = tid & 31;
  const int q0 = qt * 64;

  const int srcidx = (proj == 0) ? side : (1 - side);
  const unsigned short* xh = d_x_hi + (size_t)srcidx*XN + (size_t)b*Cc*HW;
  const unsigned short* xl = d_x_lo + (size_t)srcidx*XN + (size_t)b*Cc*HW;
  const unsigned short* wh = d_w_hi + proj*128*256;
  const unsigned short* wl = d_w_lo + proj*128*256;

  #pragma unroll
  for (int t = 0; t < 16; t++) {
    int i = tid + t*256;
    int d = i >> 5, p = (i & 31) * 8;
    uint32_t o = (uint32_t)(d*264 + p) * 2;
    cpasync16(sb32 + 0u     + o, wh + (size_t)d*256 + p);
    cpasync16(sb32 + 67584u + o, wl + (size_t)d*256 + p);
  }
  auto issue_x = [&](int buf, int c0) {
    uint32_t XB = sb32 + 135168u + (uint32_t)buf*36864u;
    #pragma unroll
    for (int t = 0; t < 4; t++) {
      int i = tid + t*256;
      int r = i >> 3, p = (i & 7) * 8;
      uint32_t o = (uint32_t)(r*STB + p) * 2;
      size_t go = (size_t)(c0 + r)*HW + q0 + p;
      cpasync16(XB + o,          xh + go);
      cpasync16(XB + 18432u + o, xl + go);
    }
  };
  issue_x(0, 0);
  CP_COMMIT();
  issue_x(1, 128);
  CP_COMMIT();

  const int dm0  = wid * 16;
  const int arow = lid & 15;
  const int akh  = (lid & 16) ? 8 : 0;
  const int trow = lid & 15;
  const int tnh  = (lid & 16) ? 8 : 0;

  float acc[8][4];
  #pragma unroll
  for (int nf = 0; nf < 8; nf++)
    #pragma unroll
    for (int e = 0; e < 4; e++) acc[nf][e] = 0.f;

  #pragma unroll 1
  for (int ch = 0; ch < 2; ch++) {
    if (ch == 0) { CP_WAIT1(); } else { CP_WAIT0(); }
    __syncthreads();
    const int cofs = ch * 128;
    const uint32_t XH = sb32 + 135168u + (uint32_t)ch*36864u;
    const uint32_t XL = XH + 18432u;
    #pragma unroll
    for (int k16 = 0; k16 < 8; k16++) {
      uint32_t ah[4], al[4];
      ldm_x4(sb32 + 0u     + ((dm0 + arow)*264 + cofs + k16*16 + akh)*2, ah);
      ldm_x4(sb32 + 67584u + ((dm0 + arow)*264 + cofs + k16*16 + akh)*2, al);
      #pragma unroll
      for (int nq = 0; nq < 4; nq++) {
        uint32_t bh[4], bl[4];
        ldm_x4_t(XH + ((k16*16 + trow)*STB + nq*16 + tnh)*2, bh);
        hmma(acc[2*nq],   ah, bh);
        hmma(acc[2*nq+1], ah, bh + 2);
        hmma(acc[2*nq],   al, bh);
        hmma(acc[2*nq+1], al, bh + 2);
        ldm_x4_t(XL + ((k16*16 + trow)*STB + nq*16 + tnh)*2, bl);
        hmma(acc[2*nq],   ah, bl);
        hmma(acc[2*nq+1], ah, bl + 2);
      }
    }
  }

  const int sb = side*NB + b;
  const int d0 = dm0 + (lid >> 2), d1 = d0 + 8;
  unsigned short* dstH;
  unsigned short* dstL;
  const float* bias;
  if (proj == 0)      { dstH = d_th_hi; dstL = d_th_lo; bias = theta_b; }
  else if (proj == 1) { dstH = d_ph_hi; dstL = d_ph_lo; bias = phi_b; }
  else                { dstH = d_g_hi;  dstL = d_g_lo;  bias = g_b; }
  size_t r0 = ((size_t)sb*Dh + d0)*HW;
  size_t r1 = ((size_t)sb*Dh + d1)*HW;
  const float b0 = bias[d0], b1 = bias[d1];

  if (proj == 0) {
    const float* pre = side ? pre_r : pre_l;
    const float* qry = side ? query_r : query_l;
    const float wl0 = theta_w[(size_t)d0*257 + 256];
    const float wl1 = theta_w[(size_t)d1*257 + 256];
    const float* q0p = qry + ((size_t)b*Dh + d0)*HW;
    const float* q1p = qry + ((size_t)b*Dh + d1)*HW;
    #pragma unroll
    for (int nf = 0; nf < 8; nf++) {
      int q = q0 + nf*8 + (lid & 3)*2;
      float2 pr = *(const float2*)&pre[(size_t)b*HW + q];
      pr.x *= (1.0f/128.0f); pr.y *= (1.0f/128.0f);
      float2 qv0 = *(const float2*)&q0p[q];
      float2 qv1 = *(const float2*)&q1p[q];
      uint32_t h, l;
      packpair(acc[nf][0] + b0 + wl0*pr.x + qv0.x,
               acc[nf][1] + b0 + wl0*pr.y + qv0.y, h, l);
      *(uint32_t*)&dstH[r0 + q] = h;
      *(uint32_t*)&dstL[r0 + q] = l;
      packpair(acc[nf][2] + b1 + wl1*pr.x + qv1.x,
               acc[nf][3] + b1 + wl1*pr.y + qv1.y, h, l);
      *(uint32_t*)&dstH[r1 + q] = h;
      *(uint32_t*)&dstL[r1 + q] = l;
    }
  } else if (proj == 1) {
    const float* kf = side ? key_l : key_r;
    const float* k0p = kf + ((size_t)b*Dh + d0)*HW;
    const float* k1p = kf + ((size_t)b*Dh + d1)*HW;
    #pragma unroll
    for (int nf = 0; nf < 8; nf++) {
      int q = q0 + nf*8 + (lid & 3)*2;
      float2 kv0 = *(const float2*)&k0p[q];
      float2 kv1 = *(const float2*)&k1p[q];
      uint32_t h, l;
      packpair(acc[nf][0] + b0 + kv0.x, acc[nf][1] + b0 + kv0.y, h, l);
      *(uint32_t*)&dstH[r0 + q] = h;
      *(uint32_t*)&dstL[r0 + q] = l;
      packpair(acc[nf][2] + b1 + kv1.x, acc[nf][3] + b1 + kv1.y, h, l);
      *(uint32_t*)&dstH[r1 + q] = h;
      *(uint32_t*)&dstL[r1 + q] = l;
    }
  } else {
    #pragma unroll
    for (int nf = 0; nf < 8; nf++) {
      int q = q0 + nf*8 + (lid & 3)*2;
      uint32_t h, l;
      packpair(acc[nf][0] + b0, acc[nf][1] + b0, h, l);
      *(uint32_t*)&dstH[r0 + q] = h;
      *(uint32_t*)&dstL[r0 + q] = l;
      packpair(acc[nf][2] + b1, acc[nf][3] + b1, h, l);
      *(uint32_t*)&dstH[r1 + q] = h;
      *(uint32_t*)&dstL[r1 + q] = l;
    }
  }
}

// ======================= fused flash attention (HMMA, split-bf16) ===============
// R16-verified: R13 structure + theta-hi register hoist. FROZEN.
#define TH_HI_OFF 0u
#define TH_LO_OFF 34816u
#define BUF_OFF   69632u     // + buf*73728: phi hi, +18432 lo, +36864 g hi, +55296 g lo
#define FL_SMEM   217088

__global__ __launch_bounds__(256, 1) void flash_kernel()
{
  extern __shared__ char smem[];
  const uint32_t sb32 = smem_u32(smem);
  const int mtile = blockIdx.x, split = blockIdx.y, sb = blockIdx.z;
  const int tid = threadIdx.x, wid = tid >> 5, lid = tid & 31;
  const int q0 = mtile * 128;
  const int kbase0 = split * (HW / KSPLIT);

  const unsigned short* thH = d_th_hi + (size_t)sb*Dh*HW + q0;
  const unsigned short* thL = d_th_lo + (size_t)sb*Dh*HW + q0;
  const unsigned short* phH = d_ph_hi + (size_t)sb*Dh*HW;
  const unsigned short* phL = d_ph_lo + (size_t)sb*Dh*HW;
  const unsigned short* gH  = d_g_hi  + (size_t)sb*Dh*HW;
  const unsigned short* gL  = d_g_lo  + (size_t)sb*Dh*HW;

  #pragma unroll
  for (int t = 0; t < 8; t++) {
    int i = tid + t*256;
    int r = i >> 4, c8 = (i & 15) * 8;
    uint32_t o = (uint32_t)(r*ST + c8) * 2;
    size_t go = (size_t)r*HW + c8;
    *(uint4*)(smem + TH_HI_OFF + o) = *(const uint4*)&thH[go];
    *(uint4*)(smem + TH_LO_OFF + o) = *(const uint4*)&thL[go];
  }

  auto issue_chunk = [&](int buf, int kb) {
    uint32_t PB = sb32 + BUF_OFF + (uint32_t)buf*73728u;
    uint32_t GB = PB + 36864u;
    #pragma unroll
    for (int t = 0; t < 4; t++) {
      int i = tid + t*256;
      int r = i >> 3, p = (i & 7) * 8;
      uint32_t o = (uint32_t)(r*STB + p) * 2;
      size_t go = (size_t)r*HW + kb + p;
      cpasync16(PB + o,          phH + go);
      cpasync16(PB + 18432u + o, phL + go);
      cpasync16(GB + o,          gH + go);
      cpasync16(GB + 18432u + o, gL + go);
    }
  };

  issue_chunk(0, kbase0);
  CP_COMMIT();

  const int m0   = wid * 16;
  const int trow = lid & 15;
  const int tnh  = (lid & 16) ? 8 : 0;
  const int brow = (lid & 7) + ((lid & 16) ? 8 : 0);
  const int bkh  = (lid & 8) ? 8 : 0;
  const float wbase = (float)((lid & 3) * 2);

  __syncthreads();
  uint32_t thA[8][4];
  #pragma unroll
  for (int k16 = 0; k16 < 8; k16++) {
    uint32_t rh[4];
    ldm_x4_t(sb32 + TH_HI_OFF + ((k16*16 + trow)*ST + m0 + tnh)*2, rh);
    thA[k16][0] = rh[0]; thA[k16][1] = rh[2];
    thA[k16][2] = rh[1]; thA[k16][3] = rh[3];
  }

  float O[16][4];
  #pragma unroll
  for (int nf = 0; nf < 16; nf++)
    #pragma unroll
    for (int e = 0; e < 4; e++) O[nf][e] = 0.f;
  float lacc0 = 0.f, lacc1 = 0.f, cacc0 = 0.f, cacc1 = 0.f;

  #pragma unroll 1
  for (int it = 0; it < NITER; it++) {
    const int buf = it & 1;
    CP_WAIT0();
    __syncthreads();

    const uint32_t PH = sb32 + BUF_OFF + (uint32_t)buf*73728u;
    const uint32_t PL = PH + 18432u;
    const uint32_t GHs = PH + 36864u;
    const uint32_t GLs = GHs + 18432u;

    float acc[8][4];
    #pragma unroll
    for (int nf = 0; nf < 8; nf++)
      #pragma unroll
      for (int e = 0; e < 4; e++) acc[nf][e] = 0.f;

    #pragma unroll
    for (int k16 = 0; k16 < 8; k16++) {
      uint32_t rl[4];
      ldm_x4_t(sb32 + TH_LO_OFF + ((k16*16 + trow)*ST + m0 + tnh)*2, rl);
      uint32_t al[4] = {rl[0], rl[2], rl[1], rl[3]};
      const uint32_t* ah = thA[k16];
      #pragma unroll
      for (int nb = 0; nb < 4; nb++) {
        uint32_t bh[4], bl[4];
        ldm_x4_t(PH + ((k16*16 + trow)*STB + nb*16 + tnh)*2, bh);
        hmma(acc[2*nb],   ah, bh);
        hmma(acc[2*nb+1], ah, bh + 2);
        hmma(acc[2*nb],   al, bh);
        hmma(acc[2*nb+1], al, bh + 2);
        ldm_x4_t(PL + ((k16*16 + trow)*STB + nb*16 + tnh)*2, bl);
        hmma(acc[2*nb],   ah, bl);
        hmma(acc[2*nb+1], ah, bl + 2);
      }
    }

    const float wof = wbase + (buf ? 64.0f : 0.0f);
    #pragma unroll
    for (int nf = 0; nf < 8; nf++) {
      float w0 = wof + (float)(nf*8), w1 = w0 + 1.0f;
      float p0 = fexp(acc[nf][0]), p1 = fexp(acc[nf][1]);
      float p2 = fexp(acc[nf][2]), p3 = fexp(acc[nf][3]);
      acc[nf][0] = p0; acc[nf][1] = p1; acc[nf][2] = p2; acc[nf][3] = p3;
      lacc0 += p0 + p1;               lacc1 += p2 + p3;
      cacc0 += p0*w0 + p1*w1;         cacc1 += p2*w0 + p3*w1;
    }

    if (it + 1 < NITER) {
      issue_chunk(buf ^ 1, kbase0 + (it + 1)*BK);
      CP_COMMIT();
    }

    #pragma unroll
    for (int kk = 0; kk < 4; kk++) {
      uint32_t a_h[4], a_l[4];
      packpair_t(acc[2*kk][0],   acc[2*kk][1],   a_h[0], a_l[0]);
      packpair_t(acc[2*kk][2],   acc[2*kk][3],   a_h[1], a_l[1]);
      packpair_t(acc[2*kk+1][0], acc[2*kk+1][1], a_h[2], a_l[2]);
      packpair_t(acc[2*kk+1][2], acc[2*kk+1][3], a_h[3], a_l[3]);
      #pragma unroll
      for (int nb = 0; nb < 8; nb++) {
        uint32_t bh[4], bl[4];
        ldm_x4(GHs + ((nb*16 + brow)*STB + kk*16 + bkh)*2, bh);
        hmma(O[2*nb],   a_h, bh);
        hmma(O[2*nb+1], a_h, bh + 2);
        hmma(O[2*nb],   a_l, bh);
        hmma(O[2*nb+1], a_l, bh + 2);
        ldm_x4(GLs + ((nb*16 + brow)*STB + kk*16 + bkh)*2, bl);
        hmma(O[2*nb],   a_h, bl);
        hmma(O[2*nb+1], a_h, bl + 2);
      }
    }
  }

  #pragma unroll
  for (int off = 1; off <= 2; off <<= 1) {
    lacc0 += __shfl_xor_sync(0xffffffffu, lacc0, off);
    lacc1 += __shfl_xor_sync(0xffffffffu, lacc1, off);
    cacc0 += __shfl_xor_sync(0xffffffffu, cacc0, off);
    cacc1 += __shfl_xor_sync(0xffffffffu, cacc1, off);
  }

  const int r0 = q0 + m0 + (lid >> 2);
  const int ssb = split*8 + sb;
  {
    float* o0 = d_op + ((size_t)ssb*HW + r0)*Dh + (lid & 3)*2;
    float* o1 = o0 + (size_t)8*Dh;
    #pragma unroll
    for (int nf = 0; nf < 16; nf++) {
      *(float2*)&o0[nf*8] = make_float2(O[nf][0], O[nf][1]);
      *(float2*)&o1[nf*8] = make_float2(O[nf][2], O[nf][3]);
    }
  }
  if ((lid & 3) == 0) {
    d_lcp[(size_t)ssb*HW + r0]     = make_float2(lacc0, cacc0);
    d_lcp[(size_t)ssb*HW + r0 + 8] = make_float2(lacc1, cacc1);
  }
}

// ======================= combine: float4 loads, higher MLP ======================
// grid (512, 8), 256 threads: 8 q per block, 32 threads per q (4 d's each)
__global__ __launch_bounds__(256) void combine_kernel(float* __restrict__ out)
{
  const int t = threadIdx.x, sb = blockIdx.y;
  const int q = blockIdx.x*8 + (t >> 5);
  const int d4 = (t & 31) * 4;
  float l = 0.f, c = 0.f;
  #pragma unroll
  for (int s = 0; s < KSPLIT; s++) {
    float2 lc = d_lcp[(size_t)(s*8 + sb)*HW + q];
    l += lc.x; c += lc.y;
  }
  float4 v = make_float4(0.f, 0.f, 0.f, 0.f);
  #pragma unroll
  for (int s = 0; s < KSPLIT; s++) {
    float4 a = *(const float4*)&d_op[((size_t)(s*8 + sb)*HW + q)*Dh + d4];
    v.x += a.x; v.y += a.y; v.z += a.z; v.w += a.w;
  }
  float inv = 1.0f / l;
  uint32_t h0, l0, h1, l1;
  packpair(v.x*inv, v.y*inv, h0, l0);
  packpair(v.z*inv, v.w*inv, h1, l1);
  size_t o = ((size_t)sb*HW + q)*Dh + d4;
  *(uint2*)&d_af_hi[o] = make_uint2(h0, h1);
  *(uint2*)&d_af_lo[o] = make_uint2(l0, l1);
  if ((t & 31) == 0)
    out[(size_t)2*NB*Cc*HW + (size_t)sb*HW + q] = (float)(q & 127) - c * inv;
}

// ======================= up-projection — HMMA (R13-verified) ====================
#define UP_SMEM 208896
__global__ __launch_bounds__(256, 1) void up_hmma_kernel(
    const float* __restrict__ up_w, const float* __restrict__ up_b)
{
  extern __shared__ char smem[];
  const uint32_t sb32 = smem_u32(smem);
  const int qtile = blockIdx.x, sb = blockIdx.y;
  const int tid = threadIdx.x, wid = tid >> 5, lid = tid & 31;
  const int q0 = qtile * 128;

  #pragma unroll
  for (int t = 0; t < 64; t++) {
    int i = tid + t*256;
    int cc = i >> 6, dd2 = (i & 63) * 2;
    float2 v = *(const float2*)&up_w[(size_t)cc*Dh + dd2];
    uint32_t h, l; packpair(v.x, v.y, h, l);
    uint32_t o = (uint32_t)(cc*ST + dd2) * 2;
    *(uint32_t*)(smem + 0u     + o) = h;
    *(uint32_t*)(smem + 69632u + o) = l;
  }
  {
    const unsigned short* bH = d_af_hi + ((size_t)sb*HW + q0)*Dh;
    const unsigned short* bL = d_af_lo + ((size_t)sb*HW + q0)*Dh;
    #pragma unroll
    for (int t = 0; t < 8; t++) {
      int i = tid + t*256;
      int r = i >> 4, c8 = (i & 15) * 8;
      uint32_t o = (uint32_t)(r*ST + c8) * 2;
      size_t go = (size_t)r*Dh + c8;
      *(uint4*)(smem + 139264u + o) = *(const uint4*)&bH[go];
      *(uint4*)(smem + 174080u + o) = *(const uint4*)&bL[go];
    }
  }
  __syncthreads();

  const int m0   = wid * 32;
  const int arow = lid & 15;
  const int akh  = (lid & 16) ? 8 : 0;
  const int brow = (lid & 7) + ((lid & 16) ? 8 : 0);
  const int bkh  = (lid & 8) ? 8 : 0;

  float acc[2][16][4];
  #pragma unroll
  for (int mf = 0; mf < 2; mf++)
    #pragma unroll
    for (int nf = 0; nf < 16; nf++)
      #pragma unroll
      for (int e = 0; e < 4; e++) acc[mf][nf][e] = 0.f;

  #pragma unroll
  for (int k16 = 0; k16 < 8; k16++) {
    uint32_t ah[2][4], al[2][4];
    #pragma unroll
    for (int mf = 0; mf < 2; mf++) {
      ldm_x4(sb32 + 0u     + ((m0 + mf*16 + arow)*ST + k16*16 + akh)*2, ah[mf]);
      ldm_x4(sb32 + 69632u + ((m0 + mf*16 + arow)*ST + k16*16 + akh)*2, al[mf]);
    }
    #pragma unroll
    for (int nb = 0; nb < 8; nb++) {
      uint32_t bh[4], bl[4];
      ldm_x4(sb32 + 139264u + ((nb*16 + brow)*ST + k16*16 + bkh)*2, bh);
      ldm_x4(sb32 + 174080u + ((nb*16 + brow)*ST + k16*16 + bkh)*2, bl);
      #pragma unroll
      for (int mf = 0; mf < 2; mf++) {
        hmma(acc[mf][2*nb],   ah[mf], bh);
        hmma(acc[mf][2*nb+1], ah[mf], bh + 2);
        hmma(acc[mf][2*nb],   al[mf], bh);
        hmma(acc[mf][2*nb+1], al[mf], bh + 2);
        hmma(acc[mf][2*nb],   ah[mf], bl);
        hmma(acc[mf][2*nb+1], ah[mf], bl + 2);
      }
    }
  }

  float* Yp = d_y + (size_t)sb*Cc*HW;
  #pragma unroll
  for (int mf = 0; mf < 2; mf++) {
    const int c0 = m0 + mf*16 + (lid >> 2);
    float bb0 = up_b[c0], bb1 = up_b[c0 + 8];
    #pragma unroll
    for (int nf = 0; nf < 16; nf++) {
      int qq = q0 + nf*8 + (lid & 3)*2;
      *(float2*)&Yp[(size_t)c0*HW + qq] =
          make_float2(acc[mf][nf][0] + bb0, acc[mf][nf][1] + bb0);
      *(float2*)&Yp[(size_t)(c0+8)*HW + qq] =
          make_float2(acc[mf][nf][2] + bb1, acc[mf][nf][3] + bb1);
    }
  }
}

// ======================= BN stats =======================
__global__ __launch_bounds__(256) void bn_stats_kernel()
{
  const int c = blockIdx.x, side = blockIdx.y;
  float s = 0.f, s2 = 0.f;
  for (int b = 0; b < NB; b++) {
    const float* p = d_y + (size_t)((side*NB + b)*Cc + c)*HW;
    for (int i = threadIdx.x; i < HW; i += 256) {
      float v = p[i];
      s += v; s2 += v*v;
    }
  }
  __shared__ float red[64];
  #pragma unroll
  for (int off = 16; off; off >>= 1) {
    s  += __shfl_down_sync(0xffffffffu, s,  off);
    s2 += __shfl_down_sync(0xffffffffu, s2, off);
  }
  int w = threadIdx.x >> 5;
  if ((threadIdx.x & 31) == 0) { red[w] = s; red[w + 32] = s2; }
  __syncthreads();
  if (threadIdx.x == 0) {
    float ts = 0.f, ts2 = 0.f;
    #pragma unroll
    for (int i = 0; i < 8; i++) { ts += red[i]; ts2 += red[i + 32]; }
    float mean = ts * (1.0f/16384.0f);
    float var  = ts2 * (1.0f/16384.0f) - mean*mean;
    d_bn[side*Cc + c] = make_float2(mean, rsqrtf(var + 1e-5f));
  }
}

// ======================= final: residual + BN apply (8 elems/thread) ============
__global__ __launch_bounds__(256) void final_kernel(
    const float* __restrict__ left, const float* __restrict__ right,
    const float* __restrict__ gamma, const float* __restrict__ beta,
    float* __restrict__ out)
{
  size_t i = ((size_t)blockIdx.x*256 + threadIdx.x) * 8;
  int q = (int)(i & 4095);
  size_t t = i >> 12;
  int c = (int)(t & 255); t >>= 8;
  int b = (int)(t & 3);
  int side = (int)(t >> 2);
  const float* x = side ? right : left;
  size_t xo = (((size_t)b*Cc + c) << 12) + q;
  // front-batch all loads for MLP
  float4 xv0 = *(const float4*)&x[xo];
  float4 xv1 = *(const float4*)&x[xo + 4];
  float4 yv0 = *(const float4*)&d_y[i];
  float4 yv1 = *(const float4*)&d_y[i + 4];
  float2 st = d_bn[side*Cc + c];
  float ga = gamma[c]*st.y;
  float be = beta[c] - ga*st.x;
  float4 r0, r1;
  r0.x = xv0.x + yv0.x*ga + be;
  r0.y = xv0.y + yv0.y*ga + be;
  r0.z = xv0.z + yv0.z*ga + be;
  r0.w = xv0.w + yv0.w*ga + be;
  r1.x = xv1.x + yv1.x*ga + be;
  r1.y = xv1.y + yv1.y*ga + be;
  r1.z = xv1.z + yv1.z*ga + be;
  r1.w = xv1.w + yv1.w*ga + be;
  *(float4*)&out[i]     = r0;
  *(float4*)&out[i + 4] = r1;
}

// ======================= launch =======================
extern "C" void kernel_launch(void* const* d_in, const int* in_sizes, int n_in,
                              void* d_out, int out_size)
{
  const float* left    = (const float*)d_in[0];
  const float* right   = (const float*)d_in[1];
  const float* pre_l   = (const float*)d_in[2];
  const float* pre_r   = (const float*)d_in[3];
  const float* query_l = (const float*)d_in[4];
  const float* key_l   = (const float*)d_in[5];
  const float* query_r = (const float*)d_in[6];
  const float* key_r   = (const float*)d_in[7];
  const float* theta_w = (const float*)d_in[8];
  const float* theta_b = (const float*)d_in[9];
  const float* phi_w   = (const float*)d_in[10];
  const float* phi_b   = (const float*)d_in[11];
  const float* g_w     = (const float*)d_in[12];
  const float* g_b     = (const float*)d_in[13];
  const float* up_w    = (const float*)d_in[14];
  const float* up_b    = (const float*)d_in[15];
  const float* bn_g    = (const float*)d_in[16];
  const float* bn_b    = (const float*)d_in[17];
  float* out = (float*)d_out;

  cudaFuncSetAttribute(proj_hmma_kernel, cudaFuncAttributeMaxDynamicSharedMemorySize, PJ_SMEM);
  cudaFuncSetAttribute(flash_kernel,     cudaFuncAttributeMaxDynamicSharedMemorySize, FL_SMEM);
  cudaFuncSetAttribute(up_hmma_kernel,   cudaFuncAttributeMaxDynamicSharedMemorySize, UP_SMEM);

  conv_kernel<<<4144, 256>>>(left, right, theta_w, phi_w, g_w);

  proj_hmma_kernel<<<dim3(64, NB, 6), 256, PJ_SMEM>>>(
      pre_l, pre_r, query_l, key_l, query_r, key_r,
      theta_w, theta_b, phi_b, g_b);

  flash_kernel<<<dim3(32, KSPLIT, 8), 256, FL_SMEM>>>();

  combine_kernel<<<dim3(512, 8), 256>>>(out);

  up_hmma_kernel<<<dim3(32, 8), 256, UP_SMEM>>>(up_w, up_b);

  bn_stats_kernel<<<dim3(Cc, 2), 256>>>();

  final_kernel<<<dim3(2*NB*Cc*HW/8/256), 256>>>(left, right, bn_g, bn_b, out);
}